// round 1
// baseline (speedup 1.0000x reference)
#include <cuda_runtime.h>
#include <cstddef>

#define N_NODES  50000
#define N_EDGES  800000
#define N_GRAPHS 512
#define IN_DIM   128
#define HID_DIM  256
#define EMB_DIM  128
#define EPS_BN   1e-5f

// ---------------- device scratch (static; no allocation allowed) ----------------
__device__ float g_agg1[(size_t)N_NODES * IN_DIM];   // A_norm(x)           [N,128]
__device__ float g_h1r [(size_t)N_NODES * HID_DIM];  // relu(agg1@W1+b1)    [N,256]
__device__ float g_h2  [(size_t)N_NODES * EMB_DIM];  // bn1(h1r)@W2         [N,128]
__device__ float g_agg2[(size_t)N_NODES * EMB_DIM];  // A_norm(h2)          [N,128]
__device__ int   g_deg [N_NODES];
__device__ float g_dinv[N_NODES];
__device__ float g_invdeg[N_NODES];
__device__ float g_sum1[HID_DIM], g_sq1[HID_DIM], g_scale1[HID_DIM], g_shift1[HID_DIM];
__device__ float g_sum2[EMB_DIM], g_sq2[EMB_DIM], g_scale2[EMB_DIM], g_shift2[EMB_DIM];

// ---------------- small utility kernels ----------------
__global__ void k_zero() {
    int i = blockIdx.x * blockDim.x + threadIdx.x;
    if (i < N_NODES) g_deg[i] = 0;
    if (i < HID_DIM) { g_sum1[i] = 0.f; g_sq1[i] = 0.f; }
    if (i < EMB_DIM) { g_sum2[i] = 0.f; g_sq2[i] = 0.f; }
}

__global__ void k_deg(const int* __restrict__ dst) {
    int e = blockIdx.x * blockDim.x + threadIdx.x;
    if (e < N_EDGES) atomicAdd(&g_deg[dst[e]], 1);
}

__global__ void k_dinv() {
    int i = blockIdx.x * blockDim.x + threadIdx.x;
    if (i < N_NODES) {
        float d = (float)g_deg[i] + 1.0f;
        g_dinv[i]   = rsqrtf(d);
        g_invdeg[i] = 1.0f / d;
    }
}

// agg[i,:] = feat[i,:] * invdeg[i]   (self-loop term; D = 128)
__global__ void k_init_agg(const float* __restrict__ feat, float* __restrict__ agg) {
    int idx = blockIdx.x * blockDim.x + threadIdx.x;      // over N*32 float4s
    if (idx >= N_NODES * 32) return;
    int i = idx >> 5;
    float w = g_invdeg[i];
    float4 v = ((const float4*)feat)[idx];
    v.x *= w; v.y *= w; v.z *= w; v.w *= w;
    ((float4*)agg)[idx] = v;
}

// one warp per edge: agg[dst] += feat[src] * dinv[src]*dinv[dst]   (D = 128)
__global__ void k_scatter(const float* __restrict__ feat, float* __restrict__ agg,
                          const int* __restrict__ src, const int* __restrict__ dst) {
    int gw = (blockIdx.x * blockDim.x + threadIdx.x) >> 5;
    if (gw >= N_EDGES) return;
    int lane = threadIdx.x & 31;
    int s = __ldg(src + gw);
    int d = __ldg(dst + gw);
    float coef = g_dinv[s] * g_dinv[d];
    float4 v = *(const float4*)(feat + (size_t)s * 128 + lane * 4);
    float* p = agg + (size_t)d * 128 + lane * 4;
    asm volatile("red.global.add.v4.f32 [%0], {%1, %2, %3, %4};"
                 :: "l"(p), "f"(v.x * coef), "f"(v.y * coef),
                    "f"(v.z * coef), "f"(v.w * coef)
                 : "memory");
}

// ---------------- tiled SGEMM: C[M,NC] = op(A)[M,KD] @ B[KD,NC] (+bias,relu) ----------------
// NORM: A element a -> a*g_scale1[k] + g_shift1[k]  (folds BatchNorm1 into layer-2 GEMM)
template <int KD, int NC, bool RELU, bool NORM>
__global__ __launch_bounds__(256) void k_mm(const float* __restrict__ A,
                                            const float* __restrict__ B,
                                            const float* __restrict__ bias,
                                            float* __restrict__ C, int M) {
    constexpr int BM = 64, BN = 64, BK = 16;
    __shared__ float As[BK][BM];
    __shared__ float Bs[BK][BN];
    int bm = blockIdx.x * BM;
    int bn = blockIdx.y * BN;
    int tid = threadIdx.x;
    int tx = tid & 15;        // column group (x4)
    int ty = tid >> 4;        // row group (x4)
    float acc[4][4] = {};

    for (int k0 = 0; k0 < KD; k0 += BK) {
        // A tile: 64 rows x 16 k, float4 per thread
        {
            int row = tid >> 2;
            int kq  = (tid & 3) * 4;
            float4 a = make_float4(0.f, 0.f, 0.f, 0.f);
            int gr = bm + row;
            if (gr < M) a = *(const float4*)(A + (size_t)gr * KD + k0 + kq);
            if (NORM) {
                a.x = a.x * g_scale1[k0 + kq + 0] + g_shift1[k0 + kq + 0];
                a.y = a.y * g_scale1[k0 + kq + 1] + g_shift1[k0 + kq + 1];
                a.z = a.z * g_scale1[k0 + kq + 2] + g_shift1[k0 + kq + 2];
                a.w = a.w * g_scale1[k0 + kq + 3] + g_shift1[k0 + kq + 3];
            }
            As[kq + 0][row] = a.x;
            As[kq + 1][row] = a.y;
            As[kq + 2][row] = a.z;
            As[kq + 3][row] = a.w;
        }
        // B tile: 16 k x 64 cols, float4 per thread
        {
            int r  = tid >> 4;
            int cq = (tid & 15) * 4;
            float4 b = *(const float4*)(B + (size_t)(k0 + r) * NC + bn + cq);
            *(float4*)&Bs[r][cq] = b;
        }
        __syncthreads();
        #pragma unroll
        for (int k = 0; k < BK; k++) {
            float4 a4 = *(const float4*)&As[k][ty * 4];
            float4 b4 = *(const float4*)&Bs[k][tx * 4];
            float ar[4] = {a4.x, a4.y, a4.z, a4.w};
            float br[4] = {b4.x, b4.y, b4.z, b4.w};
            #pragma unroll
            for (int i = 0; i < 4; i++)
                #pragma unroll
                for (int j = 0; j < 4; j++)
                    acc[i][j] = fmaf(ar[i], br[j], acc[i][j]);
        }
        __syncthreads();
    }

    #pragma unroll
    for (int i = 0; i < 4; i++) {
        int gr = bm + ty * 4 + i;
        if (gr >= M) continue;
        int gc = bn + tx * 4;
        float4 o;
        o.x = acc[i][0]; o.y = acc[i][1]; o.z = acc[i][2]; o.w = acc[i][3];
        if (RELU) {
            o.x = fmaxf(o.x + bias[gc + 0], 0.f);
            o.y = fmaxf(o.y + bias[gc + 1], 0.f);
            o.z = fmaxf(o.z + bias[gc + 2], 0.f);
            o.w = fmaxf(o.w + bias[gc + 3], 0.f);
        }
        *(float4*)(C + (size_t)gr * NC + gc) = o;
    }
}

// ---------------- batchnorm statistics ----------------
// layer 1: X = g_h1r (already relu'd), C=256
__global__ void k_stats1() {
    int c = threadIdx.x;
    float s = 0.f, ss = 0.f;
    for (int r = blockIdx.x; r < N_NODES; r += gridDim.x) {
        float v = g_h1r[(size_t)r * HID_DIM + c];
        s += v; ss += v * v;
    }
    atomicAdd(&g_sum1[c], s);
    atomicAdd(&g_sq1[c], ss);
}

// layer 2: X = relu(g_agg2 + b2), C=128
__global__ void k_stats2(const float* __restrict__ b2) {
    int c = threadIdx.x;
    float b = b2[c];
    float s = 0.f, ss = 0.f;
    for (int r = blockIdx.x; r < N_NODES; r += gridDim.x) {
        float v = fmaxf(g_agg2[(size_t)r * EMB_DIM + c] + b, 0.f);
        s += v; ss += v * v;
    }
    atomicAdd(&g_sum2[c], s);
    atomicAdd(&g_sq2[c], ss);
}

__global__ void k_bn1(const float* __restrict__ gamma, const float* __restrict__ beta) {
    int c = threadIdx.x;
    const float invM = 1.0f / (float)N_NODES;
    float m = g_sum1[c] * invM;
    float var = g_sq1[c] * invM - m * m;
    float sc = gamma[c] * rsqrtf(var + EPS_BN);
    g_scale1[c] = sc;
    g_shift1[c] = beta[c] - m * sc;
}

__global__ void k_bn2(const float* __restrict__ gamma, const float* __restrict__ beta) {
    int c = threadIdx.x;
    const float invM = 1.0f / (float)N_NODES;
    float m = g_sum2[c] * invM;
    float var = g_sq2[c] * invM - m * m;
    float sc = gamma[c] * rsqrtf(var + EPS_BN);
    g_scale2[c] = sc;
    g_shift2[c] = beta[c] - m * sc;
}

// ---------------- output: init to -inf, then atomic segment-max ----------------
__global__ void k_out_init(float* __restrict__ out) {
    int i = blockIdx.x * blockDim.x + threadIdx.x;
    if (i < N_GRAPHS * EMB_DIM) out[i] = __int_as_float(0xFF800000);
}

__global__ void k_segmax(const float* __restrict__ b2, const int* __restrict__ batch,
                         float* __restrict__ out) {
    int idx = blockIdx.x * blockDim.x + threadIdx.x;
    if (idx >= N_NODES * EMB_DIM) return;
    int i = idx >> 7;
    int c = idx & 127;
    float v = fmaxf(g_agg2[idx] + b2[c], 0.f);
    v = g_scale2[c] * v + g_shift2[c];
    int g = batch[i];
    float* addr = out + g * EMB_DIM + c;
    if (v >= 0.f) atomicMax((int*)addr, __float_as_int(v));
    else          atomicMin((unsigned int*)addr, (unsigned int)__float_as_int(v));
}

// ---------------- launch ----------------
extern "C" void kernel_launch(void* const* d_in, const int* in_sizes, int n_in,
                              void* d_out, int out_size) {
    const float* x      = (const float*)d_in[0];
    const int*   ei     = (const int*)d_in[1];
    const int*   batch  = (const int*)d_in[2];
    const float* W1     = (const float*)d_in[3];
    const float* b1     = (const float*)d_in[4];
    const float* gamma1 = (const float*)d_in[5];
    const float* beta1  = (const float*)d_in[6];
    const float* W2     = (const float*)d_in[7];
    const float* b2     = (const float*)d_in[8];
    const float* gamma2 = (const float*)d_in[9];
    const float* beta2  = (const float*)d_in[10];
    float* out = (float*)d_out;

    const int* src = ei;
    const int* dst = ei + N_EDGES;

    float *p_agg1, *p_h1r, *p_h2, *p_agg2;
    cudaGetSymbolAddress((void**)&p_agg1, g_agg1);
    cudaGetSymbolAddress((void**)&p_h1r,  g_h1r);
    cudaGetSymbolAddress((void**)&p_h2,   g_h2);
    cudaGetSymbolAddress((void**)&p_agg2, g_agg2);

    // degrees + norm coefficients
    k_zero<<<(N_NODES + 255) / 256, 256>>>();
    k_deg<<<(N_EDGES + 255) / 256, 256>>>(dst);
    k_dinv<<<(N_NODES + 255) / 256, 256>>>();

    // layer 1: aggregate x first (linearity), then GEMM
    k_init_agg<<<(N_NODES * 32 + 255) / 256, 256>>>(x, p_agg1);
    k_scatter<<<(N_EDGES * 32 + 255) / 256, 256>>>(x, p_agg1, src, dst);
    {
        dim3 grid((N_NODES + 63) / 64, HID_DIM / 64);
        k_mm<IN_DIM, HID_DIM, true, false><<<grid, 256>>>(p_agg1, W1, b1, p_h1r, N_NODES);
    }
    k_stats1<<<128, HID_DIM>>>();
    k_bn1<<<1, HID_DIM>>>(gamma1, beta1);

    // layer 2: GEMM (BN1 folded into A-load), then aggregate
    {
        dim3 grid((N_NODES + 63) / 64, EMB_DIM / 64);
        k_mm<HID_DIM, EMB_DIM, false, true><<<grid, 256>>>(p_h1r, W2, nullptr, p_h2, N_NODES);
    }
    k_init_agg<<<(N_NODES * 32 + 255) / 256, 256>>>(p_h2, p_agg2);
    k_scatter<<<(N_EDGES * 32 + 255) / 256, 256>>>(p_h2, p_agg2, src, dst);

    // BN2 stats + output segment-max
    k_stats2<<<128, EMB_DIM>>>(b2);
    k_bn2<<<1, EMB_DIM>>>(gamma2, beta2);
    k_out_init<<<(N_GRAPHS * EMB_DIM + 255) / 256, 256>>>(out);
    k_segmax<<<(N_NODES * EMB_DIM + 255) / 256, 256>>>(b2, batch, out);
}

// round 2
// speedup vs baseline: 1.3272x; 1.3272x over previous
#include <cuda_runtime.h>
#include <cstddef>

#define N_NODES  50000
#define N_EDGES  800000
#define N_GRAPHS 512
#define IN_DIM   128
#define HID_DIM  256
#define EMB_DIM  128
#define EPS_BN   1e-5f

#define SCAN_TPB 256
#define SCAN_EPB 1024
#define SCAN_NBLK ((N_NODES + SCAN_EPB - 1) / SCAN_EPB)   // 49

// ---------------- device scratch (static; no allocation allowed) ----------------
__device__ float g_agg1[(size_t)N_NODES * IN_DIM];   // A_norm(x)           [N,128]
__device__ float g_h1r [(size_t)N_NODES * HID_DIM];  // relu(agg1@W1+b1)    [N,256]
__device__ float g_h2  [(size_t)N_NODES * EMB_DIM];  // bn1(h1r)@W2         [N,128]
__device__ float g_agg2[(size_t)N_NODES * EMB_DIM];  // A_norm(h2)          [N,128]
__device__ int   g_deg [N_NODES];
__device__ int   g_rowoff[N_NODES];
__device__ int   g_cnt [N_NODES];
__device__ int   g_part[64];
__device__ int   g_csr_src[N_EDGES];
__device__ float g_coef  [N_EDGES];
__device__ float g_dinv[N_NODES];
__device__ float g_invdeg[N_NODES];
__device__ float g_sum1[HID_DIM], g_sq1[HID_DIM], g_scale1[HID_DIM], g_shift1[HID_DIM];
__device__ float g_sum2[EMB_DIM], g_sq2[EMB_DIM], g_scale2[EMB_DIM], g_shift2[EMB_DIM];

// ---------------- setup kernels ----------------
__global__ void k_zero() {
    int i = blockIdx.x * blockDim.x + threadIdx.x;
    if (i < N_NODES) { g_deg[i] = 0; g_cnt[i] = 0; }
    if (i < HID_DIM) { g_sum1[i] = 0.f; g_sq1[i] = 0.f; }
    if (i < EMB_DIM) { g_sum2[i] = 0.f; g_sq2[i] = 0.f; }
}

__global__ void k_deg(const int* __restrict__ dst) {
    int e = blockIdx.x * blockDim.x + threadIdx.x;
    if (e < N_EDGES) atomicAdd(&g_deg[dst[e]], 1);
}

__global__ void k_dinv() {
    int i = blockIdx.x * blockDim.x + threadIdx.x;
    if (i < N_NODES) {
        float d = (float)g_deg[i] + 1.0f;
        g_dinv[i]   = rsqrtf(d);
        g_invdeg[i] = 1.0f / d;
    }
}

// exclusive scan of g_deg -> g_rowoff (3-phase)
__global__ void k_scan1() {
    __shared__ int sh[SCAN_TPB / 32];
    int b = blockIdx.x, t = threadIdx.x;
    int base = b * SCAN_EPB + t * 4;
    int v[4]; int s = 0;
    #pragma unroll
    for (int q = 0; q < 4; q++) { int i = base + q; v[q] = (i < N_NODES) ? g_deg[i] : 0; s += v[q]; }
    int x = s;
    #pragma unroll
    for (int off = 1; off < 32; off <<= 1) {
        int y = __shfl_up_sync(0xffffffffu, x, off);
        if ((t & 31) >= off) x += y;
    }
    if ((t & 31) == 31) sh[t >> 5] = x;
    __syncthreads();
    if (t < 32) {
        int y = (t < SCAN_TPB / 32) ? sh[t] : 0;
        #pragma unroll
        for (int off = 1; off < SCAN_TPB / 32; off <<= 1) {
            int z = __shfl_up_sync(0xffffffffu, y, off);
            if (t >= off) y += z;
        }
        if (t < SCAN_TPB / 32) sh[t] = y;
    }
    __syncthreads();
    int warpoff = (t >= 32) ? sh[(t >> 5) - 1] : 0;
    int run = warpoff + x - s;               // exclusive prefix for this thread's 4 elems
    #pragma unroll
    for (int q = 0; q < 4; q++) { int i = base + q; if (i < N_NODES) g_rowoff[i] = run; run += v[q]; }
    if (t == SCAN_TPB - 1) g_part[b] = warpoff + x;
}

__global__ void k_scan2() {   // 1 block, 64 threads
    __shared__ int sh[64];
    int t = threadIdx.x;
    int v = (t < SCAN_NBLK) ? g_part[t] : 0;
    sh[t] = v; __syncthreads();
    for (int off = 1; off < 64; off <<= 1) {
        int y = (t >= off) ? sh[t - off] : 0;
        __syncthreads();
        sh[t] += y;
        __syncthreads();
    }
    g_part[t] = sh[t] - v;    // exclusive
}

__global__ void k_scan3() {
    int i = blockIdx.x * blockDim.x + threadIdx.x;
    if (i < N_NODES) g_rowoff[i] += g_part[i / SCAN_EPB];
}

__global__ void k_fill(const int* __restrict__ src, const int* __restrict__ dst) {
    int e = blockIdx.x * blockDim.x + threadIdx.x;
    if (e >= N_EDGES) return;
    int d = dst[e], s = src[e];
    int pos = g_rowoff[d] + atomicAdd(&g_cnt[d], 1);
    g_csr_src[pos] = s;
    g_coef[pos] = g_dinv[s] * g_dinv[d];
}

// ---------------- gather aggregation: warp per node (D = 128) ----------------
__global__ void k_gather(const float* __restrict__ feat, float* __restrict__ agg) {
    int w = (blockIdx.x * blockDim.x + threadIdx.x) >> 5;
    if (w >= N_NODES) return;
    int lane = threadIdx.x & 31;
    const float4* feat4 = (const float4*)feat;

    float4 acc = feat4[(size_t)w * 32 + lane];
    float selfw = g_invdeg[w];
    acc.x *= selfw; acc.y *= selfw; acc.z *= selfw; acc.w *= selfw;

    int start = g_rowoff[w];
    int end   = start + g_deg[w];
    for (int base = start; base < end; base += 32) {
        int e = base + lane;
        int   s_l = 0;
        float c_l = 0.f;
        if (e < end) { s_l = g_csr_src[e]; c_l = g_coef[e]; }
        int cnt = min(32, end - base);
        for (int j = 0; j < cnt; j++) {
            int   s = __shfl_sync(0xffffffffu, s_l, j);
            float c = __shfl_sync(0xffffffffu, c_l, j);
            float4 v = feat4[(size_t)s * 32 + lane];
            acc.x = fmaf(v.x, c, acc.x);
            acc.y = fmaf(v.y, c, acc.y);
            acc.z = fmaf(v.z, c, acc.z);
            acc.w = fmaf(v.w, c, acc.w);
        }
    }
    ((float4*)agg)[(size_t)w * 32 + lane] = acc;
}

// ---------------- SGEMM 128x128x8, 256 threads, 8x8/thread, double-buffered ----------------
// NORM: fold BatchNorm1 (a -> a*scale1[k]+shift1[k]) into A load
template <int KD, int NC, bool RELU, bool NORM>
__global__ __launch_bounds__(256, 2) void k_mm(const float* __restrict__ A,
                                               const float* __restrict__ B,
                                               const float* __restrict__ bias,
                                               float* __restrict__ C, int M) {
    __shared__ float As[2][8][128];
    __shared__ float Bs[2][8][128];
    const int bm = blockIdx.x * 128;
    const int bn = blockIdx.y * 128;
    const int tid = threadIdx.x;
    const int la_row = tid >> 1, la_k = (tid & 1) * 4;   // A tile load
    const int lb_row = tid >> 5, lb_col = (tid & 31) * 4; // B tile load
    const int tx = tid & 15, ty = tid >> 4;

    float acc[8][8];
    #pragma unroll
    for (int i = 0; i < 8; i++)
        #pragma unroll
        for (int j = 0; j < 8; j++) acc[i][j] = 0.f;

    auto loadA = [&](int k0) -> float4 {
        int gr = bm + la_row;
        float4 a = make_float4(0.f, 0.f, 0.f, 0.f);
        if (gr < M) a = *(const float4*)(A + (size_t)gr * KD + k0 + la_k);
        if (NORM) {
            a.x = fmaf(a.x, g_scale1[k0 + la_k + 0], g_shift1[k0 + la_k + 0]);
            a.y = fmaf(a.y, g_scale1[k0 + la_k + 1], g_shift1[k0 + la_k + 1]);
            a.z = fmaf(a.z, g_scale1[k0 + la_k + 2], g_shift1[k0 + la_k + 2]);
            a.w = fmaf(a.w, g_scale1[k0 + la_k + 3], g_shift1[k0 + la_k + 3]);
        }
        return a;
    };
    auto loadB = [&](int k0) -> float4 {
        return *(const float4*)(B + (size_t)(k0 + lb_row) * NC + bn + lb_col);
    };
    auto stash = [&](int buf, float4 a, float4 b) {
        As[buf][la_k + 0][la_row] = a.x;
        As[buf][la_k + 1][la_row] = a.y;
        As[buf][la_k + 2][la_row] = a.z;
        As[buf][la_k + 3][la_row] = a.w;
        *(float4*)&Bs[buf][lb_row][lb_col] = b;
    };
    auto compute = [&](int buf) {
        #pragma unroll
        for (int k = 0; k < 8; k++) {
            float4 a0 = *(const float4*)&As[buf][k][ty * 4];
            float4 a1 = *(const float4*)&As[buf][k][ty * 4 + 64];
            float4 b0 = *(const float4*)&Bs[buf][k][tx * 4];
            float4 b1 = *(const float4*)&Bs[buf][k][tx * 4 + 64];
            float ar[8] = {a0.x, a0.y, a0.z, a0.w, a1.x, a1.y, a1.z, a1.w};
            float br[8] = {b0.x, b0.y, b0.z, b0.w, b1.x, b1.y, b1.z, b1.w};
            #pragma unroll
            for (int i = 0; i < 8; i++)
                #pragma unroll
                for (int j = 0; j < 8; j++)
                    acc[i][j] = fmaf(ar[i], br[j], acc[i][j]);
        }
    };

    float4 ar = loadA(0), br = loadB(0);
    stash(0, ar, br);
    __syncthreads();
    int buf = 0;
    for (int k0 = 8; k0 < KD; k0 += 8) {
        ar = loadA(k0); br = loadB(k0);
        compute(buf);
        stash(buf ^ 1, ar, br);
        __syncthreads();
        buf ^= 1;
    }
    compute(buf);

    // epilogue
    #pragma unroll
    for (int half = 0; half < 2; half++) {
        #pragma unroll
        for (int i = 0; i < 4; i++) {
            int gr = bm + ty * 4 + half * 64 + i;
            if (gr >= M) continue;
            #pragma unroll
            for (int chalf = 0; chalf < 2; chalf++) {
                int gc = bn + tx * 4 + chalf * 64;
                float4 o;
                o.x = acc[half * 4 + i][chalf * 4 + 0];
                o.y = acc[half * 4 + i][chalf * 4 + 1];
                o.z = acc[half * 4 + i][chalf * 4 + 2];
                o.w = acc[half * 4 + i][chalf * 4 + 3];
                if (RELU) {
                    o.x = fmaxf(o.x + bias[gc + 0], 0.f);
                    o.y = fmaxf(o.y + bias[gc + 1], 0.f);
                    o.z = fmaxf(o.z + bias[gc + 2], 0.f);
                    o.w = fmaxf(o.w + bias[gc + 3], 0.f);
                }
                *(float4*)(C + (size_t)gr * NC + gc) = o;
            }
        }
    }
}

// ---------------- batchnorm statistics ----------------
__global__ void k_stats1() {
    int c = threadIdx.x;
    float s = 0.f, ss = 0.f;
    for (int r = blockIdx.x; r < N_NODES; r += gridDim.x) {
        float v = g_h1r[(size_t)r * HID_DIM + c];
        s += v; ss += v * v;
    }
    atomicAdd(&g_sum1[c], s);
    atomicAdd(&g_sq1[c], ss);
}

__global__ void k_stats2(const float* __restrict__ b2) {
    int c = threadIdx.x;
    float b = b2[c];
    float s = 0.f, ss = 0.f;
    for (int r = blockIdx.x; r < N_NODES; r += gridDim.x) {
        float v = fmaxf(g_agg2[(size_t)r * EMB_DIM + c] + b, 0.f);
        s += v; ss += v * v;
    }
    atomicAdd(&g_sum2[c], s);
    atomicAdd(&g_sq2[c], ss);
}

__global__ void k_bn1(const float* __restrict__ gamma, const float* __restrict__ beta) {
    int c = threadIdx.x;
    const float invM = 1.0f / (float)N_NODES;
    float m = g_sum1[c] * invM;
    float var = g_sq1[c] * invM - m * m;
    float sc = gamma[c] * rsqrtf(var + EPS_BN);
    g_scale1[c] = sc;
    g_shift1[c] = beta[c] - m * sc;
}

__global__ void k_bn2(const float* __restrict__ gamma, const float* __restrict__ beta) {
    int c = threadIdx.x;
    const float invM = 1.0f / (float)N_NODES;
    float m = g_sum2[c] * invM;
    float var = g_sq2[c] * invM - m * m;
    float sc = gamma[c] * rsqrtf(var + EPS_BN);
    g_scale2[c] = sc;
    g_shift2[c] = beta[c] - m * sc;
}

// ---------------- output ----------------
__global__ void k_out_init(float* __restrict__ out) {
    int i = blockIdx.x * blockDim.x + threadIdx.x;
    if (i < N_GRAPHS * EMB_DIM) out[i] = __int_as_float(0xFF800000);
}

__global__ void k_segmax(const float* __restrict__ b2, const int* __restrict__ batch,
                         float* __restrict__ out) {
    int idx = blockIdx.x * blockDim.x + threadIdx.x;
    if (idx >= N_NODES * EMB_DIM) return;
    int i = idx >> 7;
    int c = idx & 127;
    float v = fmaxf(g_agg2[idx] + b2[c], 0.f);
    v = g_scale2[c] * v + g_shift2[c];
    int g = batch[i];
    float* addr = out + g * EMB_DIM + c;
    if (v >= 0.f) atomicMax((int*)addr, __float_as_int(v));
    else          atomicMin((unsigned int*)addr, (unsigned int)__float_as_int(v));
}

// ---------------- launch ----------------
extern "C" void kernel_launch(void* const* d_in, const int* in_sizes, int n_in,
                              void* d_out, int out_size) {
    const float* x      = (const float*)d_in[0];
    const int*   ei     = (const int*)d_in[1];
    const int*   batch  = (const int*)d_in[2];
    const float* W1     = (const float*)d_in[3];
    const float* b1     = (const float*)d_in[4];
    const float* gamma1 = (const float*)d_in[5];
    const float* beta1  = (const float*)d_in[6];
    const float* W2     = (const float*)d_in[7];
    const float* b2     = (const float*)d_in[8];
    const float* gamma2 = (const float*)d_in[9];
    const float* beta2  = (const float*)d_in[10];
    float* out = (float*)d_out;

    const int* src = ei;
    const int* dst = ei + N_EDGES;

    float *p_agg1, *p_h1r, *p_h2, *p_agg2;
    cudaGetSymbolAddress((void**)&p_agg1, g_agg1);
    cudaGetSymbolAddress((void**)&p_h1r,  g_h1r);
    cudaGetSymbolAddress((void**)&p_h2,   g_h2);
    cudaGetSymbolAddress((void**)&p_agg2, g_agg2);

    // degrees + CSR build
    k_zero<<<(N_NODES + 255) / 256, 256>>>();
    k_deg<<<(N_EDGES + 255) / 256, 256>>>(dst);
    k_dinv<<<(N_NODES + 255) / 256, 256>>>();
    k_scan1<<<SCAN_NBLK, SCAN_TPB>>>();
    k_scan2<<<1, 64>>>();
    k_scan3<<<(N_NODES + 255) / 256, 256>>>();
    k_fill<<<(N_EDGES + 255) / 256, 256>>>(src, dst);

    // layer 1: aggregate x first (linearity), then GEMM (+bias+relu)
    k_gather<<<(N_NODES * 32 + 255) / 256, 256>>>(x, p_agg1);
    {
        dim3 grid((N_NODES + 127) / 128, HID_DIM / 128);
        k_mm<IN_DIM, HID_DIM, true, false><<<grid, 256>>>(p_agg1, W1, b1, p_h1r, N_NODES);
    }
    k_stats1<<<128, HID_DIM>>>();
    k_bn1<<<1, HID_DIM>>>(gamma1, beta1);

    // layer 2: GEMM (BN1 folded into A-load), then aggregate
    {
        dim3 grid((N_NODES + 127) / 128, EMB_DIM / 128);
        k_mm<HID_DIM, EMB_DIM, false, true><<<grid, 256>>>(p_h1r, W2, nullptr, p_h2, N_NODES);
    }
    k_gather<<<(N_NODES * 32 + 255) / 256, 256>>>(p_h2, p_agg2);

    // BN2 stats + output segment-max
    k_stats2<<<128, EMB_DIM>>>(b2);
    k_bn2<<<1, EMB_DIM>>>(gamma2, beta2);
    k_out_init<<<(N_GRAPHS * EMB_DIM + 255) / 256, 256>>>(out);
    k_segmax<<<(N_NODES * EMB_DIM + 255) / 256, 256>>>(b2, batch, out);
}

// round 4
// speedup vs baseline: 1.5759x; 1.1874x over previous
#include <cuda_runtime.h>
#include <cstdint>
#include <cstddef>

#define N_NODES  50000
#define N_EDGES  800000
#define N_GRAPHS 512
#define IN_DIM   128
#define HID_DIM  256
#define EMB_DIM  128
#define EPS_BN   1e-5f

#define SCAN_TPB 256
#define SCAN_EPB 1024
#define SCAN_NBLK ((N_NODES + SCAN_EPB - 1) / SCAN_EPB)   // 49

// ---------------- device scratch (static; no allocation allowed) ----------------
__device__ float g_agg1[(size_t)N_NODES * IN_DIM];   // A_norm(x)           [N,128]
__device__ float g_h1r [(size_t)N_NODES * HID_DIM];  // relu(agg1@W1+b1)    [N,256]
__device__ float g_h2  [(size_t)N_NODES * EMB_DIM];  // bn1(h1r)@W2         [N,128]
__device__ float g_agg2[(size_t)N_NODES * EMB_DIM];  // A_norm(h2)          [N,128]
__device__ int   g_deg [N_NODES];
__device__ int   g_rowoff[N_NODES];
__device__ int   g_cnt [N_NODES];
__device__ int   g_part[64];
__device__ int   g_csr_src[N_EDGES];
__device__ float g_coef  [N_EDGES];
__device__ float g_dinv[N_NODES];
__device__ float g_invdeg[N_NODES];
__device__ float g_sum1[HID_DIM], g_sq1[HID_DIM], g_scale1[HID_DIM], g_shift1[HID_DIM];
__device__ float g_sum2[EMB_DIM], g_sq2[EMB_DIM], g_scale2[EMB_DIM], g_shift2[EMB_DIM];

// ---------------- setup kernels ----------------
__global__ void k_zero() {
    int i = blockIdx.x * blockDim.x + threadIdx.x;
    if (i < N_NODES) { g_deg[i] = 0; g_cnt[i] = 0; }
    if (i < HID_DIM) { g_sum1[i] = 0.f; g_sq1[i] = 0.f; }
    if (i < EMB_DIM) { g_sum2[i] = 0.f; g_sq2[i] = 0.f; }
}

__global__ void k_deg(const int* __restrict__ dst) {
    int e = blockIdx.x * blockDim.x + threadIdx.x;
    if (e < N_EDGES) atomicAdd(&g_deg[dst[e]], 1);
}

__global__ void k_dinv() {
    int i = blockIdx.x * blockDim.x + threadIdx.x;
    if (i < N_NODES) {
        float d = (float)g_deg[i] + 1.0f;
        g_dinv[i]   = rsqrtf(d);
        g_invdeg[i] = 1.0f / d;
    }
}

// exclusive scan of g_deg -> g_rowoff (3-phase)
__global__ void k_scan1() {
    __shared__ int sh[SCAN_TPB / 32];
    int b = blockIdx.x, t = threadIdx.x;
    int base = b * SCAN_EPB + t * 4;
    int v[4]; int s = 0;
    #pragma unroll
    for (int q = 0; q < 4; q++) { int i = base + q; v[q] = (i < N_NODES) ? g_deg[i] : 0; s += v[q]; }
    int x = s;
    #pragma unroll
    for (int off = 1; off < 32; off <<= 1) {
        int y = __shfl_up_sync(0xffffffffu, x, off);
        if ((t & 31) >= off) x += y;
    }
    if ((t & 31) == 31) sh[t >> 5] = x;
    __syncthreads();
    if (t < 32) {
        int y = (t < SCAN_TPB / 32) ? sh[t] : 0;
        #pragma unroll
        for (int off = 1; off < SCAN_TPB / 32; off <<= 1) {
            int z = __shfl_up_sync(0xffffffffu, y, off);
            if (t >= off) y += z;
        }
        if (t < SCAN_TPB / 32) sh[t] = y;
    }
    __syncthreads();
    int warpoff = (t >= 32) ? sh[(t >> 5) - 1] : 0;
    int run = warpoff + x - s;
    #pragma unroll
    for (int q = 0; q < 4; q++) { int i = base + q; if (i < N_NODES) g_rowoff[i] = run; run += v[q]; }
    if (t == SCAN_TPB - 1) g_part[b] = warpoff + x;
}

__global__ void k_scan2() {
    __shared__ int sh[64];
    int t = threadIdx.x;
    int v = (t < SCAN_NBLK) ? g_part[t] : 0;
    sh[t] = v; __syncthreads();
    for (int off = 1; off < 64; off <<= 1) {
        int y = (t >= off) ? sh[t - off] : 0;
        __syncthreads();
        sh[t] += y;
        __syncthreads();
    }
    g_part[t] = sh[t] - v;
}

__global__ void k_scan3() {
    int i = blockIdx.x * blockDim.x + threadIdx.x;
    if (i < N_NODES) g_rowoff[i] += g_part[i / SCAN_EPB];
}

__global__ void k_fill(const int* __restrict__ src, const int* __restrict__ dst) {
    int e = blockIdx.x * blockDim.x + threadIdx.x;
    if (e >= N_EDGES) return;
    int d = dst[e], s = src[e];
    int pos = g_rowoff[d] + atomicAdd(&g_cnt[d], 1);
    g_csr_src[pos] = s;
    g_coef[pos] = g_dinv[s] * g_dinv[d];
}

// ---------------- gather aggregation: warp per node (D = 128) ----------------
__global__ void k_gather(const float* __restrict__ feat, float* __restrict__ agg) {
    int w = (blockIdx.x * blockDim.x + threadIdx.x) >> 5;
    if (w >= N_NODES) return;
    int lane = threadIdx.x & 31;
    const float4* feat4 = (const float4*)feat;

    float4 acc = feat4[(size_t)w * 32 + lane];
    float selfw = g_invdeg[w];
    acc.x *= selfw; acc.y *= selfw; acc.z *= selfw; acc.w *= selfw;

    int start = g_rowoff[w];
    int end   = start + g_deg[w];
    for (int base = start; base < end; base += 32) {
        int e = base + lane;
        int   s_l = 0;
        float c_l = 0.f;
        if (e < end) { s_l = g_csr_src[e]; c_l = g_coef[e]; }
        int cnt = min(32, end - base);
        for (int j = 0; j < cnt; j++) {
            int   s = __shfl_sync(0xffffffffu, s_l, j);
            float c = __shfl_sync(0xffffffffu, c_l, j);
            float4 v = feat4[(size_t)s * 32 + lane];
            acc.x = fmaf(v.x, c, acc.x);
            acc.y = fmaf(v.y, c, acc.y);
            acc.z = fmaf(v.z, c, acc.z);
            acc.w = fmaf(v.w, c, acc.w);
        }
    }
    ((float4*)agg)[(size_t)w * 32 + lane] = acc;
}

// ================= tf32 mma.sync GEMM (sm_80+ PTX, no tcgen05) =================
__device__ __forceinline__ uint32_t f2tf32(float f) {
    uint32_t r; asm("cvt.rna.tf32.f32 %0, %1;" : "=r"(r) : "f"(f)); return r;
}
__device__ __forceinline__ void mma8(float& c0, float& c1, float& c2, float& c3,
                                     uint32_t a0, uint32_t a1, uint32_t a2, uint32_t a3,
                                     uint32_t b0, uint32_t b1) {
    asm volatile(
        "mma.sync.aligned.m16n8k8.row.col.f32.tf32.tf32.f32 "
        "{%0,%1,%2,%3}, {%4,%5,%6,%7}, {%8,%9}, {%0,%1,%2,%3};"
        : "+f"(c0), "+f"(c1), "+f"(c2), "+f"(c3)
        : "r"(a0), "r"(a1), "r"(a2), "r"(a3), "r"(b0), "r"(b1));
}

// C[M,NC] = (NORM? bn1(A) : A)[M,KD] @ W[KD,NC] (+bias,relu)
// CTA tile 128x128; 8 warps in 4(M) x 2(N); warp tile 32x64; tf32 HMMA.
// Smem: B tile [KD][136] (tf32), A chunk [32][136] x2 (tf32, [k][row]).
template <int KD, int NC, bool RELU, bool NORM>
__global__ __launch_bounds__(256) void k_mma(const float* __restrict__ A,
                                             const float* __restrict__ W,
                                             const float* __restrict__ bias,
                                             float* __restrict__ C, int M) {
    constexpr int STR = 136;             // stride (floats): 136 % 32 == 8 -> conflict-free frags
    constexpr int NCHUNK = KD / 32;
    extern __shared__ uint32_t smem_u[];
    uint32_t* Bs = smem_u;               // KD * STR
    uint32_t* As = smem_u + KD * STR;    // 2 * 32 * STR

    const int tid  = threadIdx.x;
    const int wid  = tid >> 5;
    const int lane = tid & 31;
    const int g = lane >> 2, t = lane & 3;
    const int wm = wid & 3, wn = wid >> 2;
    const int bm = blockIdx.x * 128;
    const int bn = blockIdx.y * 128;

    // ---- load B tile (cols [bn,bn+128)) as tf32 ----
    for (int i = tid; i < KD * 32; i += 256) {     // KD*128/4 float4s
        int k = i >> 5;
        int n = (i & 31) * 4;
        float4 w = *(const float4*)(W + (size_t)k * NC + bn + n);
        Bs[k * STR + n + 0] = f2tf32(w.x);
        Bs[k * STR + n + 1] = f2tf32(w.y);
        Bs[k * STR + n + 2] = f2tf32(w.z);
        Bs[k * STR + n + 3] = f2tf32(w.w);
    }

    const int la_row = tid >> 1;
    const int la_k   = (tid & 1) * 16;
    const int gr_a   = bm + la_row;

    float acc[2][8][4];
    #pragma unroll
    for (int f = 0; f < 2; f++)
        #pragma unroll
        for (int j = 0; j < 8; j++)
            #pragma unroll
            for (int q = 0; q < 4; q++) acc[f][j][q] = 0.f;

    auto loadA = [&](int c, float4* pre) {
        int k0 = c * 32 + la_k;
        #pragma unroll
        for (int i = 0; i < 4; i++) {
            float4 v = make_float4(0.f, 0.f, 0.f, 0.f);
            if (gr_a < M) v = *(const float4*)(A + (size_t)gr_a * KD + k0 + i * 4);
            if (NORM) {
                int kk = k0 + i * 4;
                v.x = fmaf(v.x, g_scale1[kk + 0], g_shift1[kk + 0]);
                v.y = fmaf(v.y, g_scale1[kk + 1], g_shift1[kk + 1]);
                v.z = fmaf(v.z, g_scale1[kk + 2], g_shift1[kk + 2]);
                v.w = fmaf(v.w, g_scale1[kk + 3], g_shift1[kk + 3]);
            }
            pre[i] = v;
        }
    };
    auto storeA = [&](int buf, const float4* pre) {
        uint32_t* Ab = As + buf * (32 * STR);
        #pragma unroll
        for (int i = 0; i < 4; i++) {
            int kl = la_k + i * 4;
            Ab[(kl + 0) * STR + la_row] = f2tf32(pre[i].x);
            Ab[(kl + 1) * STR + la_row] = f2tf32(pre[i].y);
            Ab[(kl + 2) * STR + la_row] = f2tf32(pre[i].z);
            Ab[(kl + 3) * STR + la_row] = f2tf32(pre[i].w);
        }
    };
    auto compute = [&](int buf, int c) {
        const uint32_t* Ab = As + buf * (32 * STR);
        #pragma unroll
        for (int ks = 0; ks < 4; ks++) {
            int kt = ks * 8 + t;
            uint32_t a[2][4];
            #pragma unroll
            for (int f = 0; f < 2; f++) {
                int row = wm * 32 + f * 16 + g;
                a[f][0] = Ab[kt * STR + row];
                a[f][1] = Ab[kt * STR + row + 8];
                a[f][2] = Ab[(kt + 4) * STR + row];
                a[f][3] = Ab[(kt + 4) * STR + row + 8];
            }
            int kabs = c * 32 + ks * 8 + t;
            #pragma unroll
            for (int j = 0; j < 8; j++) {
                int col = wn * 64 + j * 8 + g;
                uint32_t b0 = Bs[kabs * STR + col];
                uint32_t b1 = Bs[(kabs + 4) * STR + col];
                mma8(acc[0][j][0], acc[0][j][1], acc[0][j][2], acc[0][j][3],
                     a[0][0], a[0][1], a[0][2], a[0][3], b0, b1);
                mma8(acc[1][j][0], acc[1][j][1], acc[1][j][2], acc[1][j][3],
                     a[1][0], a[1][1], a[1][2], a[1][3], b0, b1);
            }
        }
    };

    float4 pre[4];
    loadA(0, pre);
    storeA(0, pre);
    __syncthreads();
    int buf = 0;
    for (int c = 1; c < NCHUNK; c++) {
        loadA(c, pre);
        compute(buf, c - 1);
        storeA(buf ^ 1, pre);
        __syncthreads();
        buf ^= 1;
    }
    compute(buf, NCHUNK - 1);

    // ---- epilogue: regs -> gmem (+bias,relu) ----
    #pragma unroll
    for (int f = 0; f < 2; f++) {
        int r0 = bm + wm * 32 + f * 16 + g;
        #pragma unroll
        for (int j = 0; j < 8; j++) {
            int gc = bn + wn * 64 + j * 8 + 2 * t;
            float2 v0 = make_float2(acc[f][j][0], acc[f][j][1]);
            float2 v1 = make_float2(acc[f][j][2], acc[f][j][3]);
            if (RELU) {
                float b0v = bias[gc], b1v = bias[gc + 1];
                v0.x = fmaxf(v0.x + b0v, 0.f); v0.y = fmaxf(v0.y + b1v, 0.f);
                v1.x = fmaxf(v1.x + b0v, 0.f); v1.y = fmaxf(v1.y + b1v, 0.f);
            }
            if (r0 < M)     *(float2*)(C + (size_t)r0 * NC + gc)       = v0;
            if (r0 + 8 < M) *(float2*)(C + (size_t)(r0 + 8) * NC + gc) = v1;
        }
    }
}

// ---------------- batchnorm statistics ----------------
__global__ void k_stats1() {
    int c = threadIdx.x;
    float s = 0.f, ss = 0.f;
    for (int r = blockIdx.x; r < N_NODES; r += gridDim.x) {
        float v = g_h1r[(size_t)r * HID_DIM + c];
        s += v; ss += v * v;
    }
    atomicAdd(&g_sum1[c], s);
    atomicAdd(&g_sq1[c], ss);
}

__global__ void k_stats2(const float* __restrict__ b2) {
    int c = threadIdx.x;
    float b = b2[c];
    float s = 0.f, ss = 0.f;
    for (int r = blockIdx.x; r < N_NODES; r += gridDim.x) {
        float v = fmaxf(g_agg2[(size_t)r * EMB_DIM + c] + b, 0.f);
        s += v; ss += v * v;
    }
    atomicAdd(&g_sum2[c], s);
    atomicAdd(&g_sq2[c], ss);
}

__global__ void k_bn1(const float* __restrict__ gamma, const float* __restrict__ beta) {
    int c = threadIdx.x;
    const float invM = 1.0f / (float)N_NODES;
    float m = g_sum1[c] * invM;
    float var = g_sq1[c] * invM - m * m;
    float sc = gamma[c] * rsqrtf(var + EPS_BN);
    g_scale1[c] = sc;
    g_shift1[c] = beta[c] - m * sc;
}

__global__ void k_bn2(const float* __restrict__ gamma, const float* __restrict__ beta) {
    int c = threadIdx.x;
    const float invM = 1.0f / (float)N_NODES;
    float m = g_sum2[c] * invM;
    float var = g_sq2[c] * invM - m * m;
    float sc = gamma[c] * rsqrtf(var + EPS_BN);
    g_scale2[c] = sc;
    g_shift2[c] = beta[c] - m * sc;
}

// ---------------- output ----------------
__global__ void k_out_init(float* __restrict__ out) {
    int i = blockIdx.x * blockDim.x + threadIdx.x;
    if (i < N_GRAPHS * EMB_DIM) out[i] = __int_as_float(0xFF800000);
}

__global__ void k_segmax(const float* __restrict__ b2, const int* __restrict__ batch,
                         float* __restrict__ out) {
    int idx = blockIdx.x * blockDim.x + threadIdx.x;
    if (idx >= N_NODES * EMB_DIM) return;
    int i = idx >> 7;
    int c = idx & 127;
    float v = fmaxf(g_agg2[idx] + b2[c], 0.f);
    v = g_scale2[c] * v + g_shift2[c];
    int g = batch[i];
    float* addr = out + g * EMB_DIM + c;
    if (v >= 0.f) atomicMax((int*)addr, __float_as_int(v));
    else          atomicMin((unsigned int*)addr, (unsigned int)__float_as_int(v));
}

// ---------------- launch ----------------
extern "C" void kernel_launch(void* const* d_in, const int* in_sizes, int n_in,
                              void* d_out, int out_size) {
    const float* x      = (const float*)d_in[0];
    const int*   ei     = (const int*)d_in[1];
    const int*   batch  = (const int*)d_in[2];
    const float* W1     = (const float*)d_in[3];
    const float* b1     = (const float*)d_in[4];
    const float* gamma1 = (const float*)d_in[5];
    const float* beta1  = (const float*)d_in[6];
    const float* W2     = (const float*)d_in[7];
    const float* b2     = (const float*)d_in[8];
    const float* gamma2 = (const float*)d_in[9];
    const float* beta2  = (const float*)d_in[10];
    float* out = (float*)d_out;

    const int* src = ei;
    const int* dst = ei + N_EDGES;

    float *p_agg1, *p_h1r, *p_h2, *p_agg2;
    cudaGetSymbolAddress((void**)&p_agg1, g_agg1);
    cudaGetSymbolAddress((void**)&p_h1r,  g_h1r);
    cudaGetSymbolAddress((void**)&p_h2,   g_h2);
    cudaGetSymbolAddress((void**)&p_agg2, g_agg2);

    const int SMEM1 = (IN_DIM * 136 + 2 * 32 * 136) * 4;   // 104448
    const int SMEM2 = (HID_DIM * 136 + 2 * 32 * 136) * 4;  // 174080
    cudaFuncSetAttribute(k_mma<IN_DIM, HID_DIM, true, false>,
                         cudaFuncAttributeMaxDynamicSharedMemorySize, SMEM1);
    cudaFuncSetAttribute(k_mma<HID_DIM, EMB_DIM, false, true>,
                         cudaFuncAttributeMaxDynamicSharedMemorySize, SMEM2);
    const int MTILES = (N_NODES + 127) / 128;              // 391

    // degrees + CSR build
    k_zero<<<(N_NODES + 255) / 256, 256>>>();
    k_deg<<<(N_EDGES + 255) / 256, 256>>>(dst);
    k_dinv<<<(N_NODES + 255) / 256, 256>>>();
    k_scan1<<<SCAN_NBLK, SCAN_TPB>>>();
    k_scan2<<<1, 64>>>();
    k_scan3<<<(N_NODES + 255) / 256, 256>>>();
    k_fill<<<(N_EDGES + 255) / 256, 256>>>(src, dst);

    // layer 1: aggregate x first (linearity), then tf32 tensor GEMM (+bias+relu)
    k_gather<<<(N_NODES * 32 + 255) / 256, 256>>>(x, p_agg1);
    {
        dim3 grid(MTILES, HID_DIM / 128);
        k_mma<IN_DIM, HID_DIM, true, false><<<grid, 256, SMEM1>>>(p_agg1, W1, b1, p_h1r, N_NODES);
    }
    k_stats1<<<128, HID_DIM>>>();
    k_bn1<<<1, HID_DIM>>>(gamma1, beta1);

    // layer 2: tf32 GEMM (BN1 folded into A staging), then aggregate
    {
        dim3 grid(MTILES, EMB_DIM / 128);
        k_mma<HID_DIM, EMB_DIM, false, true><<<grid, 256, SMEM2>>>(p_h1r, W2, nullptr, p_h2, N_NODES);
    }
    k_gather<<<(N_NODES * 32 + 255) / 256, 256>>>(p_h2, p_agg2);

    // BN2 stats + output segment-max
    k_stats2<<<128, EMB_DIM>>>(b2);
    k_bn2<<<1, EMB_DIM>>>(gamma2, beta2);
    k_out_init<<<(N_GRAPHS * EMB_DIM + 255) / 256, 256>>>(out);
    k_segmax<<<(N_NODES * EMB_DIM + 255) / 256, 256>>>(b2, batch, out);
}

// round 5
// speedup vs baseline: 1.5787x; 1.0018x over previous
#include <cuda_runtime.h>
#include <cstdint>
#include <cstddef>

#define N_NODES  50000
#define N_EDGES  800000
#define N_GRAPHS 512
#define IN_DIM   128
#define HID_DIM  256
#define EMB_DIM  128
#define EPS_BN   1e-5f

#define SCAN_TPB 256
#define SCAN_EPB 1024
#define SCAN_NBLK ((N_NODES + SCAN_EPB - 1) / SCAN_EPB)   // 49

// ---------------- device scratch (static; no allocation allowed) ----------------
__device__ float g_agg1[(size_t)N_NODES * IN_DIM];   // A_norm(x)           [N,128]
__device__ float g_h1r [(size_t)N_NODES * HID_DIM];  // relu(agg1@W1+b1)    [N,256]
__device__ float g_h2  [(size_t)N_NODES * EMB_DIM];  // bn1(h1r)@W2         [N,128]
__device__ float g_agg2[(size_t)N_NODES * EMB_DIM];  // A_norm(h2)          [N,128]
__device__ int   g_deg [N_NODES];
__device__ int   g_rowoff[N_NODES];
__device__ int   g_cnt [N_NODES];
__device__ int   g_part[64];
__device__ int   g_csr_src[N_EDGES];
__device__ float g_coef  [N_EDGES];
__device__ float g_dinv[N_NODES];
__device__ float g_invdeg[N_NODES];
__device__ float g_sum1[HID_DIM], g_sq1[HID_DIM], g_scale1[HID_DIM], g_shift1[HID_DIM];
__device__ float g_sum2[EMB_DIM], g_sq2[EMB_DIM], g_scale2[EMB_DIM], g_shift2[EMB_DIM];

// ---------------- setup kernels ----------------
__global__ void k_zero() {
    int i = blockIdx.x * blockDim.x + threadIdx.x;
    if (i < N_NODES) { g_deg[i] = 0; g_cnt[i] = 0; }
    if (i < HID_DIM) { g_sum1[i] = 0.f; g_sq1[i] = 0.f; }
    if (i < EMB_DIM) { g_sum2[i] = 0.f; g_sq2[i] = 0.f; }
}

__global__ void k_deg(const int* __restrict__ dst) {
    int e = blockIdx.x * blockDim.x + threadIdx.x;
    if (e < N_EDGES) atomicAdd(&g_deg[dst[e]], 1);
}

__global__ void k_dinv() {
    int i = blockIdx.x * blockDim.x + threadIdx.x;
    if (i < N_NODES) {
        float d = (float)g_deg[i] + 1.0f;
        g_dinv[i]   = rsqrtf(d);
        g_invdeg[i] = 1.0f / d;
    }
}

// exclusive scan of g_deg -> g_rowoff (3-phase)
__global__ void k_scan1() {
    __shared__ int sh[SCAN_TPB / 32];
    int b = blockIdx.x, t = threadIdx.x;
    int base = b * SCAN_EPB + t * 4;
    int v[4]; int s = 0;
    #pragma unroll
    for (int q = 0; q < 4; q++) { int i = base + q; v[q] = (i < N_NODES) ? g_deg[i] : 0; s += v[q]; }
    int x = s;
    #pragma unroll
    for (int off = 1; off < 32; off <<= 1) {
        int y = __shfl_up_sync(0xffffffffu, x, off);
        if ((t & 31) >= off) x += y;
    }
    if ((t & 31) == 31) sh[t >> 5] = x;
    __syncthreads();
    if (t < 32) {
        int y = (t < SCAN_TPB / 32) ? sh[t] : 0;
        #pragma unroll
        for (int off = 1; off < SCAN_TPB / 32; off <<= 1) {
            int z = __shfl_up_sync(0xffffffffu, y, off);
            if (t >= off) y += z;
        }
        if (t < SCAN_TPB / 32) sh[t] = y;
    }
    __syncthreads();
    int warpoff = (t >= 32) ? sh[(t >> 5) - 1] : 0;
    int run = warpoff + x - s;
    #pragma unroll
    for (int q = 0; q < 4; q++) { int i = base + q; if (i < N_NODES) g_rowoff[i] = run; run += v[q]; }
    if (t == SCAN_TPB - 1) g_part[b] = warpoff + x;
}

__global__ void k_scan2() {
    __shared__ int sh[64];
    int t = threadIdx.x;
    int v = (t < SCAN_NBLK) ? g_part[t] : 0;
    sh[t] = v; __syncthreads();
    for (int off = 1; off < 64; off <<= 1) {
        int y = (t >= off) ? sh[t - off] : 0;
        __syncthreads();
        sh[t] += y;
        __syncthreads();
    }
    g_part[t] = sh[t] - v;
}

__global__ void k_scan3() {
    int i = blockIdx.x * blockDim.x + threadIdx.x;
    if (i < N_NODES) g_rowoff[i] += g_part[i / SCAN_EPB];
}

__global__ void k_fill(const int* __restrict__ src, const int* __restrict__ dst) {
    int e = blockIdx.x * blockDim.x + threadIdx.x;
    if (e >= N_EDGES) return;
    int d = dst[e], s = src[e];
    int pos = g_rowoff[d] + atomicAdd(&g_cnt[d], 1);
    g_csr_src[pos] = s;
    g_coef[pos] = g_dinv[s] * g_dinv[d];
}

// ---------------- gather aggregation: warp per node (D = 128) ----------------
__global__ void k_gather(const float* __restrict__ feat, float* __restrict__ agg) {
    int w = (blockIdx.x * blockDim.x + threadIdx.x) >> 5;
    if (w >= N_NODES) return;
    int lane = threadIdx.x & 31;
    const float4* feat4 = (const float4*)feat;

    float4 acc = feat4[(size_t)w * 32 + lane];
    float selfw = g_invdeg[w];
    acc.x *= selfw; acc.y *= selfw; acc.z *= selfw; acc.w *= selfw;

    int start = g_rowoff[w];
    int end   = start + g_deg[w];
    for (int base = start; base < end; base += 32) {
        int e = base + lane;
        int   s_l = 0;
        float c_l = 0.f;
        if (e < end) { s_l = g_csr_src[e]; c_l = g_coef[e]; }
        int cnt = min(32, end - base);
        for (int j = 0; j < cnt; j++) {
            int   s = __shfl_sync(0xffffffffu, s_l, j);
            float c = __shfl_sync(0xffffffffu, c_l, j);
            float4 v = feat4[(size_t)s * 32 + lane];
            acc.x = fmaf(v.x, c, acc.x);
            acc.y = fmaf(v.y, c, acc.y);
            acc.z = fmaf(v.z, c, acc.z);
            acc.w = fmaf(v.w, c, acc.w);
        }
    }
    ((float4*)agg)[(size_t)w * 32 + lane] = acc;
}

// ================= tf32 mma.sync GEMM (sm_80+ PTX, no tcgen05) =================
__device__ __forceinline__ uint32_t f2tf32(float f) {
    uint32_t r; asm("cvt.rna.tf32.f32 %0, %1;" : "=r"(r) : "f"(f)); return r;
}
__device__ __forceinline__ void mma8(float& c0, float& c1, float& c2, float& c3,
                                     uint32_t a0, uint32_t a1, uint32_t a2, uint32_t a3,
                                     uint32_t b0, uint32_t b1) {
    asm volatile(
        "mma.sync.aligned.m16n8k8.row.col.f32.tf32.tf32.f32 "
        "{%0,%1,%2,%3}, {%4,%5,%6,%7}, {%8,%9}, {%0,%1,%2,%3};"
        : "+f"(c0), "+f"(c1), "+f"(c2), "+f"(c3)
        : "r"(a0), "r"(a1), "r"(a2), "r"(a3), "r"(b0), "r"(b1));
}

// C[M,NC] = (NORM? bn1(A) : A)[M,KD] @ W[KD,NC] (+bias,relu)
// CTA tile 128x128; 8 warps in 4(M) x 2(N); warp tile 32x64; tf32 HMMA.
// Smem: B tile [KD][136] (tf32), A chunk [32][136] x2 (tf32, [k][row]).
template <int KD, int NC, bool RELU, bool NORM>
__global__ __launch_bounds__(256) void k_mma(const float* __restrict__ A,
                                             const float* __restrict__ W,
                                             const float* __restrict__ bias,
                                             float* __restrict__ C, int M) {
    constexpr int STR = 136;             // stride (floats): 136 % 32 == 8 -> conflict-free frags
    constexpr int NCHUNK = KD / 32;
    extern __shared__ uint32_t smem_u[];
    uint32_t* Bs = smem_u;               // KD * STR
    uint32_t* As = smem_u + KD * STR;    // 2 * 32 * STR

    const int tid  = threadIdx.x;
    const int wid  = tid >> 5;
    const int lane = tid & 31;
    const int g = lane >> 2, t = lane & 3;
    const int wm = wid & 3, wn = wid >> 2;
    const int bm = blockIdx.x * 128;
    const int bn = blockIdx.y * 128;

    // ---- load B tile (cols [bn,bn+128)) as tf32 ----
    for (int i = tid; i < KD * 32; i += 256) {     // KD*128/4 float4s
        int k = i >> 5;
        int n = (i & 31) * 4;
        float4 w = *(const float4*)(W + (size_t)k * NC + bn + n);
        Bs[k * STR + n + 0] = f2tf32(w.x);
        Bs[k * STR + n + 1] = f2tf32(w.y);
        Bs[k * STR + n + 2] = f2tf32(w.z);
        Bs[k * STR + n + 3] = f2tf32(w.w);
    }

    const int la_row = tid >> 1;
    const int la_k   = (tid & 1) * 16;
    const int gr_a   = bm + la_row;

    float acc[2][8][4];
    #pragma unroll
    for (int f = 0; f < 2; f++)
        #pragma unroll
        for (int j = 0; j < 8; j++)
            #pragma unroll
            for (int q = 0; q < 4; q++) acc[f][j][q] = 0.f;

    auto loadA = [&](int c, float4* pre) {
        int k0 = c * 32 + la_k;
        #pragma unroll
        for (int i = 0; i < 4; i++) {
            float4 v = make_float4(0.f, 0.f, 0.f, 0.f);
            if (gr_a < M) v = *(const float4*)(A + (size_t)gr_a * KD + k0 + i * 4);
            if (NORM) {
                int kk = k0 + i * 4;
                v.x = fmaf(v.x, g_scale1[kk + 0], g_shift1[kk + 0]);
                v.y = fmaf(v.y, g_scale1[kk + 1], g_shift1[kk + 1]);
                v.z = fmaf(v.z, g_scale1[kk + 2], g_shift1[kk + 2]);
                v.w = fmaf(v.w, g_scale1[kk + 3], g_shift1[kk + 3]);
            }
            pre[i] = v;
        }
    };
    auto storeA = [&](int buf, const float4* pre) {
        uint32_t* Ab = As + buf * (32 * STR);
        #pragma unroll
        for (int i = 0; i < 4; i++) {
            int kl = la_k + i * 4;
            Ab[(kl + 0) * STR + la_row] = f2tf32(pre[i].x);
            Ab[(kl + 1) * STR + la_row] = f2tf32(pre[i].y);
            Ab[(kl + 2) * STR + la_row] = f2tf32(pre[i].z);
            Ab[(kl + 3) * STR + la_row] = f2tf32(pre[i].w);
        }
    };
    auto compute = [&](int buf, int c) {
        const uint32_t* Ab = As + buf * (32 * STR);
        #pragma unroll
        for (int ks = 0; ks < 4; ks++) {
            int kt = ks * 8 + t;
            uint32_t a[2][4];
            #pragma unroll
            for (int f = 0; f < 2; f++) {
                int row = wm * 32 + f * 16 + g;
                a[f][0] = Ab[kt * STR + row];
                a[f][1] = Ab[kt * STR + row + 8];
                a[f][2] = Ab[(kt + 4) * STR + row];
                a[f][3] = Ab[(kt + 4) * STR + row + 8];
            }
            int kabs = c * 32 + ks * 8 + t;
            #pragma unroll
            for (int j = 0; j < 8; j++) {
                int col = wn * 64 + j * 8 + g;
                uint32_t b0 = Bs[kabs * STR + col];
                uint32_t b1 = Bs[(kabs + 4) * STR + col];
                mma8(acc[0][j][0], acc[0][j][1], acc[0][j][2], acc[0][j][3],
                     a[0][0], a[0][1], a[0][2], a[0][3], b0, b1);
                mma8(acc[1][j][0], acc[1][j][1], acc[1][j][2], acc[1][j][3],
                     a[1][0], a[1][1], a[1][2], a[1][3], b0, b1);
            }
        }
    };

    float4 pre[4];
    loadA(0, pre);
    storeA(0, pre);
    __syncthreads();
    int buf = 0;
    for (int c = 1; c < NCHUNK; c++) {
        loadA(c, pre);
        compute(buf, c - 1);
        storeA(buf ^ 1, pre);
        __syncthreads();
        buf ^= 1;
    }
    compute(buf, NCHUNK - 1);

    // ---- epilogue: regs -> gmem (+bias,relu) ----
    #pragma unroll
    for (int f = 0; f < 2; f++) {
        int r0 = bm + wm * 32 + f * 16 + g;
        #pragma unroll
        for (int j = 0; j < 8; j++) {
            int gc = bn + wn * 64 + j * 8 + 2 * t;
            float2 v0 = make_float2(acc[f][j][0], acc[f][j][1]);
            float2 v1 = make_float2(acc[f][j][2], acc[f][j][3]);
            if (RELU) {
                float b0v = bias[gc], b1v = bias[gc + 1];
                v0.x = fmaxf(v0.x + b0v, 0.f); v0.y = fmaxf(v0.y + b1v, 0.f);
                v1.x = fmaxf(v1.x + b0v, 0.f); v1.y = fmaxf(v1.y + b1v, 0.f);
            }
            if (r0 < M)     *(float2*)(C + (size_t)r0 * NC + gc)       = v0;
            if (r0 + 8 < M) *(float2*)(C + (size_t)(r0 + 8) * NC + gc) = v1;
        }
    }
}

// ---------------- batchnorm statistics ----------------
__global__ void k_stats1() {
    int c = threadIdx.x;
    float s = 0.f, ss = 0.f;
    for (int r = blockIdx.x; r < N_NODES; r += gridDim.x) {
        float v = g_h1r[(size_t)r * HID_DIM + c];
        s += v; ss += v * v;
    }
    atomicAdd(&g_sum1[c], s);
    atomicAdd(&g_sq1[c], ss);
}

__global__ void k_stats2(const float* __restrict__ b2) {
    int c = threadIdx.x;
    float b = b2[c];
    float s = 0.f, ss = 0.f;
    for (int r = blockIdx.x; r < N_NODES; r += gridDim.x) {
        float v = fmaxf(g_agg2[(size_t)r * EMB_DIM + c] + b, 0.f);
        s += v; ss += v * v;
    }
    atomicAdd(&g_sum2[c], s);
    atomicAdd(&g_sq2[c], ss);
}

__global__ void k_bn1(const float* __restrict__ gamma, const float* __restrict__ beta) {
    int c = threadIdx.x;
    const float invM = 1.0f / (float)N_NODES;
    float m = g_sum1[c] * invM;
    float var = g_sq1[c] * invM - m * m;
    float sc = gamma[c] * rsqrtf(var + EPS_BN);
    g_scale1[c] = sc;
    g_shift1[c] = beta[c] - m * sc;
}

__global__ void k_bn2(const float* __restrict__ gamma, const float* __restrict__ beta) {
    int c = threadIdx.x;
    const float invM = 1.0f / (float)N_NODES;
    float m = g_sum2[c] * invM;
    float var = g_sq2[c] * invM - m * m;
    float sc = gamma[c] * rsqrtf(var + EPS_BN);
    g_scale2[c] = sc;
    g_shift2[c] = beta[c] - m * sc;
}

// ---------------- output ----------------
__global__ void k_out_init(float* __restrict__ out) {
    int i = blockIdx.x * blockDim.x + threadIdx.x;
    if (i < N_GRAPHS * EMB_DIM) out[i] = __int_as_float(0xFF800000);
}

__global__ void k_segmax(const float* __restrict__ b2, const int* __restrict__ batch,
                         float* __restrict__ out) {
    int idx = blockIdx.x * blockDim.x + threadIdx.x;
    if (idx >= N_NODES * EMB_DIM) return;
    int i = idx >> 7;
    int c = idx & 127;
    float v = fmaxf(g_agg2[idx] + b2[c], 0.f);
    v = g_scale2[c] * v + g_shift2[c];
    int g = batch[i];
    float* addr = out + g * EMB_DIM + c;
    if (v >= 0.f) atomicMax((int*)addr, __float_as_int(v));
    else          atomicMin((unsigned int*)addr, (unsigned int)__float_as_int(v));
}

// ---------------- launch ----------------
extern "C" void kernel_launch(void* const* d_in, const int* in_sizes, int n_in,
                              void* d_out, int out_size) {
    const float* x      = (const float*)d_in[0];
    const int*   ei     = (const int*)d_in[1];
    const int*   batch  = (const int*)d_in[2];
    const float* W1     = (const float*)d_in[3];
    const float* b1     = (const float*)d_in[4];
    const float* gamma1 = (const float*)d_in[5];
    const float* beta1  = (const float*)d_in[6];
    const float* W2     = (const float*)d_in[7];
    const float* b2     = (const float*)d_in[8];
    const float* gamma2 = (const float*)d_in[9];
    const float* beta2  = (const float*)d_in[10];
    float* out = (float*)d_out;

    const int* src = ei;
    const int* dst = ei + N_EDGES;

    float *p_agg1, *p_h1r, *p_h2, *p_agg2;
    cudaGetSymbolAddress((void**)&p_agg1, g_agg1);
    cudaGetSymbolAddress((void**)&p_h1r,  g_h1r);
    cudaGetSymbolAddress((void**)&p_h2,   g_h2);
    cudaGetSymbolAddress((void**)&p_agg2, g_agg2);

    const int SMEM1 = (IN_DIM * 136 + 2 * 32 * 136) * 4;   // 104448
    const int SMEM2 = (HID_DIM * 136 + 2 * 32 * 136) * 4;  // 174080
    cudaFuncSetAttribute(k_mma<IN_DIM, HID_DIM, true, false>,
                         cudaFuncAttributeMaxDynamicSharedMemorySize, SMEM1);
    cudaFuncSetAttribute(k_mma<HID_DIM, EMB_DIM, false, true>,
                         cudaFuncAttributeMaxDynamicSharedMemorySize, SMEM2);
    const int MTILES = (N_NODES + 127) / 128;              // 391

    // degrees + CSR build
    k_zero<<<(N_NODES + 255) / 256, 256>>>();
    k_deg<<<(N_EDGES + 255) / 256, 256>>>(dst);
    k_dinv<<<(N_NODES + 255) / 256, 256>>>();
    k_scan1<<<SCAN_NBLK, SCAN_TPB>>>();
    k_scan2<<<1, 64>>>();
    k_scan3<<<(N_NODES + 255) / 256, 256>>>();
    k_fill<<<(N_EDGES + 255) / 256, 256>>>(src, dst);

    // layer 1: aggregate x first (linearity), then tf32 tensor GEMM (+bias+relu)
    k_gather<<<(N_NODES * 32 + 255) / 256, 256>>>(x, p_agg1);
    {
        dim3 grid(MTILES, HID_DIM / 128);
        k_mma<IN_DIM, HID_DIM, true, false><<<grid, 256, SMEM1>>>(p_agg1, W1, b1, p_h1r, N_NODES);
    }
    k_stats1<<<128, HID_DIM>>>();
    k_bn1<<<1, HID_DIM>>>(gamma1, beta1);

    // layer 2: tf32 GEMM (BN1 folded into A staging), then aggregate
    {
        dim3 grid(MTILES, EMB_DIM / 128);
        k_mma<HID_DIM, EMB_DIM, false, true><<<grid, 256, SMEM2>>>(p_h1r, W2, nullptr, p_h2, N_NODES);
    }
    k_gather<<<(N_NODES * 32 + 255) / 256, 256>>>(p_h2, p_agg2);

    // BN2 stats + output segment-max
    k_stats2<<<128, EMB_DIM>>>(b2);
    k_bn2<<<1, EMB_DIM>>>(gamma2, beta2);
    k_out_init<<<(N_GRAPHS * EMB_DIM + 255) / 256, 256>>>(out);
    k_segmax<<<(N_NODES * EMB_DIM + 255) / 256, 256>>>(b2, batch, out);
}

// round 6
// speedup vs baseline: 2.1815x; 1.3819x over previous
#include <cuda_runtime.h>
#include <cstdint>
#include <cstddef>

#define N_NODES  50000
#define N_EDGES  800000
#define N_GRAPHS 512
#define IN_DIM   128
#define HID_DIM  256
#define EMB_DIM  128
#define EPS_BN   1e-5f

#define SCAN_TPB 256
#define SCAN_EPB 1024
#define SCAN_NBLK ((N_NODES + SCAN_EPB - 1) / SCAN_EPB)   // 49

// ---------------- device scratch (static; no allocation allowed) ----------------
__device__ float g_agg1[(size_t)N_NODES * IN_DIM];   // A_norm(x)                 [N,128]
__device__ float g_h1r [(size_t)N_NODES * HID_DIM];  // relu(agg1@W1+b1)          [N,256]
__device__ float g_h2  [(size_t)N_NODES * EMB_DIM];  // bn1(h1r)@W2               [N,128]
__device__ float g_agg2[(size_t)N_NODES * EMB_DIM];  // relu(A_norm(h2)+b2)       [N,128]
__device__ int   g_deg [N_NODES];
__device__ int   g_rowoff[N_NODES];
__device__ int   g_cnt [N_NODES];
__device__ int   g_part[64];
__device__ int   g_csr_src[N_EDGES];
__device__ float g_coef  [N_EDGES];
__device__ float g_dinv[N_NODES];
__device__ float g_invdeg[N_NODES];
__device__ float g_sum1[HID_DIM], g_sq1[HID_DIM];
__device__ float g_sum2[EMB_DIM], g_sq2[EMB_DIM];

// ---------------- setup kernels ----------------
__global__ void k_zero(float* __restrict__ out) {
    int i = blockIdx.x * blockDim.x + threadIdx.x;
    if (i < N_NODES) { g_deg[i] = 0; g_cnt[i] = 0; }
    if (i < HID_DIM) { g_sum1[i] = 0.f; g_sq1[i] = 0.f; }
    if (i < EMB_DIM) { g_sum2[i] = 0.f; g_sq2[i] = 0.f; }
    if (i < N_GRAPHS * EMB_DIM) out[i] = __int_as_float(0xFF800000);
}

__global__ void k_deg(const int* __restrict__ dst) {
    int e = blockIdx.x * blockDim.x + threadIdx.x;
    if (e < N_EDGES) atomicAdd(&g_deg[dst[e]], 1);
}

// exclusive scan of g_deg -> g_rowoff (3-phase); also computes dinv/invdeg
__global__ void k_scan1() {
    __shared__ int sh[SCAN_TPB / 32];
    int b = blockIdx.x, t = threadIdx.x;
    int base = b * SCAN_EPB + t * 4;
    int v[4]; int s = 0;
    #pragma unroll
    for (int q = 0; q < 4; q++) {
        int i = base + q;
        v[q] = (i < N_NODES) ? g_deg[i] : 0;
        s += v[q];
        if (i < N_NODES) {
            float d = (float)v[q] + 1.0f;
            g_dinv[i]   = rsqrtf(d);
            g_invdeg[i] = 1.0f / d;
        }
    }
    int x = s;
    #pragma unroll
    for (int off = 1; off < 32; off <<= 1) {
        int y = __shfl_up_sync(0xffffffffu, x, off);
        if ((t & 31) >= off) x += y;
    }
    if ((t & 31) == 31) sh[t >> 5] = x;
    __syncthreads();
    if (t < 32) {
        int y = (t < SCAN_TPB / 32) ? sh[t] : 0;
        #pragma unroll
        for (int off = 1; off < SCAN_TPB / 32; off <<= 1) {
            int z = __shfl_up_sync(0xffffffffu, y, off);
            if (t >= off) y += z;
        }
        if (t < SCAN_TPB / 32) sh[t] = y;
    }
    __syncthreads();
    int warpoff = (t >= 32) ? sh[(t >> 5) - 1] : 0;
    int run = warpoff + x - s;
    #pragma unroll
    for (int q = 0; q < 4; q++) { int i = base + q; if (i < N_NODES) g_rowoff[i] = run; run += v[q]; }
    if (t == SCAN_TPB - 1) g_part[b] = warpoff + x;
}

__global__ void k_scan2() {
    __shared__ int sh[64];
    int t = threadIdx.x;
    int v = (t < SCAN_NBLK) ? g_part[t] : 0;
    sh[t] = v; __syncthreads();
    for (int off = 1; off < 64; off <<= 1) {
        int y = (t >= off) ? sh[t - off] : 0;
        __syncthreads();
        sh[t] += y;
        __syncthreads();
    }
    g_part[t] = sh[t] - v;
}

__global__ void k_scan3() {
    int i = blockIdx.x * blockDim.x + threadIdx.x;
    if (i < N_NODES) g_rowoff[i] += g_part[i / SCAN_EPB];
}

__global__ void k_fill(const int* __restrict__ src, const int* __restrict__ dst) {
    int e = blockIdx.x * blockDim.x + threadIdx.x;
    if (e >= N_EDGES) return;
    int d = dst[e], s = src[e];
    int pos = g_rowoff[d] + atomicAdd(&g_cnt[d], 1);
    g_csr_src[pos] = s;
    g_coef[pos] = g_dinv[s] * g_dinv[d];
}

// ---------------- gather aggregation: warp per node (D = 128) ----------------
// STATS2: apply +bias, relu before storing; accumulate column sum/sumsq into g_sum2/g_sq2.
template <bool STATS2>
__global__ void k_gather(const float* __restrict__ feat, float* __restrict__ agg,
                         const float* __restrict__ bias) {
    __shared__ float ssum[STATS2 ? 128 : 1];
    __shared__ float ssq [STATS2 ? 128 : 1];
    int tid = threadIdx.x;
    if (STATS2) {
        if (tid < 128) { ssum[tid] = 0.f; ssq[tid] = 0.f; }
        __syncthreads();
    }
    int w = (blockIdx.x * blockDim.x + tid) >> 5;
    int lane = tid & 31;
    const float4* feat4 = (const float4*)feat;

    float4 acc = feat4[(size_t)w * 32 + lane];
    float selfw = g_invdeg[w];
    acc.x *= selfw; acc.y *= selfw; acc.z *= selfw; acc.w *= selfw;

    int start = g_rowoff[w];
    int end   = start + g_deg[w];
    for (int base = start; base < end; base += 32) {
        int e = base + lane;
        int   s_l = 0;
        float c_l = 0.f;
        if (e < end) { s_l = g_csr_src[e]; c_l = g_coef[e]; }
        int cnt = min(32, end - base);
        for (int j = 0; j < cnt; j++) {
            int   s = __shfl_sync(0xffffffffu, s_l, j);
            float c = __shfl_sync(0xffffffffu, c_l, j);
            float4 v = feat4[(size_t)s * 32 + lane];
            acc.x = fmaf(v.x, c, acc.x);
            acc.y = fmaf(v.y, c, acc.y);
            acc.z = fmaf(v.z, c, acc.z);
            acc.w = fmaf(v.w, c, acc.w);
        }
    }
    if (STATS2) {
        float4 b = ((const float4*)bias)[lane];
        acc.x = fmaxf(acc.x + b.x, 0.f);
        acc.y = fmaxf(acc.y + b.y, 0.f);
        acc.z = fmaxf(acc.z + b.z, 0.f);
        acc.w = fmaxf(acc.w + b.w, 0.f);
    }
    ((float4*)agg)[(size_t)w * 32 + lane] = acc;
    if (STATS2) {
        atomicAdd(&ssum[lane * 4 + 0], acc.x);
        atomicAdd(&ssum[lane * 4 + 1], acc.y);
        atomicAdd(&ssum[lane * 4 + 2], acc.z);
        atomicAdd(&ssum[lane * 4 + 3], acc.w);
        atomicAdd(&ssq[lane * 4 + 0], acc.x * acc.x);
        atomicAdd(&ssq[lane * 4 + 1], acc.y * acc.y);
        atomicAdd(&ssq[lane * 4 + 2], acc.z * acc.z);
        atomicAdd(&ssq[lane * 4 + 3], acc.w * acc.w);
        __syncthreads();
        if (tid < 128) {
            atomicAdd(&g_sum2[tid], ssum[tid]);
            atomicAdd(&g_sq2[tid], ssq[tid]);
        }
    }
}

// ================= tf32 mma.sync GEMM =================
__device__ __forceinline__ uint32_t f2tf32(float f) {
    uint32_t r; asm("cvt.rna.tf32.f32 %0, %1;" : "=r"(r) : "f"(f)); return r;
}
__device__ __forceinline__ void mma8(float& c0, float& c1, float& c2, float& c3,
                                     uint32_t a0, uint32_t a1, uint32_t a2, uint32_t a3,
                                     uint32_t b0, uint32_t b1) {
    asm volatile(
        "mma.sync.aligned.m16n8k8.row.col.f32.tf32.tf32.f32 "
        "{%0,%1,%2,%3}, {%4,%5,%6,%7}, {%8,%9}, {%0,%1,%2,%3};"
        : "+f"(c0), "+f"(c1), "+f"(c2), "+f"(c3)
        : "r"(a0), "r"(a1), "r"(a2), "r"(a3), "r"(b0), "r"(b1));
}

// C[M,NC] = (NORM? bn1(A) : A)[M,KD] @ W[KD,NC] (+bias,relu)
// CTA tile 128x128; 8 warps 4(M)x2(N); warp tile 32x64; tf32 HMMA.
// STATS: accumulate column sum/sumsq of relu'd C into g_sum1/g_sq1 (masked to rows < M).
// NORM: compute scale/shift from g_sum1/g_sq1 + gamma/beta into smem, apply to A.
template <int KD, int NC, bool RELU, bool NORM, bool STATS>
__global__ __launch_bounds__(256) void k_mma(const float* __restrict__ A,
                                             const float* __restrict__ W,
                                             const float* __restrict__ bias,
                                             const float* __restrict__ gamma,
                                             const float* __restrict__ beta,
                                             float* __restrict__ C, int M) {
    constexpr int STR = 136;
    constexpr int NCHUNK = KD / 32;
    extern __shared__ uint32_t smem_u[];
    uint32_t* Bs = smem_u;               // KD * STR
    uint32_t* As = smem_u + KD * STR;    // 2 * 32 * STR
    float* sc1 = (float*)(smem_u + KD * STR + 2 * 32 * STR);       // [KD] when NORM
    float* sh1 = sc1 + (NORM ? KD : 0);

    const int tid  = threadIdx.x;
    const int wid  = tid >> 5;
    const int lane = tid & 31;
    const int g = lane >> 2, t = lane & 3;
    const int wm = wid & 3, wn = wid >> 2;
    const int bm = blockIdx.x * 128;
    const int bn = blockIdx.y * 128;

    if (NORM) {
        const float invM = 1.0f / (float)N_NODES;
        for (int i = tid; i < KD; i += 256) {
            float m = g_sum1[i] * invM;
            float var = g_sq1[i] * invM - m * m;
            float sc = gamma[i] * rsqrtf(var + EPS_BN);
            sc1[i] = sc;
            sh1[i] = beta[i] - m * sc;
        }
    }

    // ---- load B tile (cols [bn,bn+128)) as tf32 ----
    for (int i = tid; i < KD * 32; i += 256) {
        int k = i >> 5;
        int n = (i & 31) * 4;
        float4 w = *(const float4*)(W + (size_t)k * NC + bn + n);
        uint4 u;
        u.x = f2tf32(w.x); u.y = f2tf32(w.y); u.z = f2tf32(w.z); u.w = f2tf32(w.w);
        *(uint4*)&Bs[k * STR + n] = u;
    }

    const int la_row = tid >> 1;
    const int la_k   = (tid & 1) * 16;
    const int gr_a   = bm + la_row;

    float acc[2][8][4];
    #pragma unroll
    for (int f = 0; f < 2; f++)
        #pragma unroll
        for (int j = 0; j < 8; j++)
            #pragma unroll
            for (int q = 0; q < 4; q++) acc[f][j][q] = 0.f;

    auto loadA = [&](int c, float4* pre) {
        int k0 = c * 32 + la_k;
        #pragma unroll
        for (int i = 0; i < 4; i++) {
            float4 v = make_float4(0.f, 0.f, 0.f, 0.f);
            if (gr_a < M) v = *(const float4*)(A + (size_t)gr_a * KD + k0 + i * 4);
            if (NORM) {
                int kk = k0 + i * 4;
                v.x = fmaf(v.x, sc1[kk + 0], sh1[kk + 0]);
                v.y = fmaf(v.y, sc1[kk + 1], sh1[kk + 1]);
                v.z = fmaf(v.z, sc1[kk + 2], sh1[kk + 2]);
                v.w = fmaf(v.w, sc1[kk + 3], sh1[kk + 3]);
            }
            pre[i] = v;
        }
    };
    auto storeA = [&](int buf, const float4* pre) {
        uint32_t* Ab = As + buf * (32 * STR);
        #pragma unroll
        for (int i = 0; i < 4; i++) {
            int kl = la_k + i * 4;
            Ab[(kl + 0) * STR + la_row] = f2tf32(pre[i].x);
            Ab[(kl + 1) * STR + la_row] = f2tf32(pre[i].y);
            Ab[(kl + 2) * STR + la_row] = f2tf32(pre[i].z);
            Ab[(kl + 3) * STR + la_row] = f2tf32(pre[i].w);
        }
    };
    auto compute = [&](int buf, int c) {
        const uint32_t* Ab = As + buf * (32 * STR);
        #pragma unroll
        for (int ks = 0; ks < 4; ks++) {
            int kt = ks * 8 + t;
            uint32_t a[2][4];
            #pragma unroll
            for (int f = 0; f < 2; f++) {
                int row = wm * 32 + f * 16 + g;
                a[f][0] = Ab[kt * STR + row];
                a[f][1] = Ab[kt * STR + row + 8];
                a[f][2] = Ab[(kt + 4) * STR + row];
                a[f][3] = Ab[(kt + 4) * STR + row + 8];
            }
            int kabs = c * 32 + ks * 8 + t;
            #pragma unroll
            for (int j = 0; j < 8; j++) {
                int col = wn * 64 + j * 8 + g;
                uint32_t b0 = Bs[kabs * STR + col];
                uint32_t b1 = Bs[(kabs + 4) * STR + col];
                mma8(acc[0][j][0], acc[0][j][1], acc[0][j][2], acc[0][j][3],
                     a[0][0], a[0][1], a[0][2], a[0][3], b0, b1);
                mma8(acc[1][j][0], acc[1][j][1], acc[1][j][2], acc[1][j][3],
                     a[1][0], a[1][1], a[1][2], a[1][3], b0, b1);
            }
        }
    };

    float4 pre[4];
    loadA(0, pre);
    if (NORM) __syncthreads();   // sc1/sh1 visible before loadA(0)? loadA(0) above already read
    // NOTE: when NORM, loadA(0) ran before sync — redo it to be safe
    if (NORM) loadA(0, pre);
    storeA(0, pre);
    __syncthreads();
    int buf = 0;
    for (int c = 1; c < NCHUNK; c++) {
        loadA(c, pre);
        compute(buf, c - 1);
        storeA(buf ^ 1, pre);
        __syncthreads();
        buf ^= 1;
    }
    compute(buf, NCHUNK - 1);

    // ---- epilogue: regs -> gmem (+bias,relu) ; fused stats ----
    #pragma unroll
    for (int f = 0; f < 2; f++) {
        int r0 = bm + wm * 32 + f * 16 + g;
        #pragma unroll
        for (int j = 0; j < 8; j++) {
            int gc = bn + wn * 64 + j * 8 + 2 * t;
            float2 v0 = make_float2(acc[f][j][0], acc[f][j][1]);
            float2 v1 = make_float2(acc[f][j][2], acc[f][j][3]);
            if (RELU) {
                float b0v = bias[gc], b1v = bias[gc + 1];
                v0.x = fmaxf(v0.x + b0v, 0.f); v0.y = fmaxf(v0.y + b1v, 0.f);
                v1.x = fmaxf(v1.x + b0v, 0.f); v1.y = fmaxf(v1.y + b1v, 0.f);
            }
            if (r0 < M)     *(float2*)(C + (size_t)r0 * NC + gc)       = v0;
            if (r0 + 8 < M) *(float2*)(C + (size_t)(r0 + 8) * NC + gc) = v1;
            if (STATS) {
                bool m0 = r0 < M, m1 = (r0 + 8) < M;
                float s0 = (m0 ? v0.x : 0.f) + (m1 ? v1.x : 0.f);
                float s1 = (m0 ? v0.y : 0.f) + (m1 ? v1.y : 0.f);
                float q0 = (m0 ? v0.x * v0.x : 0.f) + (m1 ? v1.x * v1.x : 0.f);
                float q1 = (m0 ? v0.y * v0.y : 0.f) + (m1 ? v1.y * v1.y : 0.f);
                #pragma unroll
                for (int off = 4; off < 32; off <<= 1) {
                    s0 += __shfl_xor_sync(0xffffffffu, s0, off);
                    s1 += __shfl_xor_sync(0xffffffffu, s1, off);
                    q0 += __shfl_xor_sync(0xffffffffu, q0, off);
                    q1 += __shfl_xor_sync(0xffffffffu, q1, off);
                }
                if (lane < 4) {
                    int cc = bn + wn * 64 + j * 8 + 2 * lane;
                    atomicAdd(&g_sum1[cc], s0);
                    atomicAdd(&g_sum1[cc + 1], s1);
                    atomicAdd(&g_sq1[cc], q0);
                    atomicAdd(&g_sq1[cc + 1], q1);
                }
            }
        }
    }
}

// ---------------- output: segment-max with fused BN2 ----------------
__global__ void k_segmax(const float* __restrict__ gamma, const float* __restrict__ beta,
                         const int* __restrict__ batch, float* __restrict__ out) {
    __shared__ float sc[EMB_DIM], sh[EMB_DIM];
    int tid = threadIdx.x;
    if (tid < EMB_DIM) {
        const float invM = 1.0f / (float)N_NODES;
        float m = g_sum2[tid] * invM;
        float var = g_sq2[tid] * invM - m * m;
        float s = gamma[tid] * rsqrtf(var + EPS_BN);
        sc[tid] = s;
        sh[tid] = beta[tid] - m * s;
    }
    __syncthreads();
    int idx = blockIdx.x * blockDim.x + tid;
    if (idx >= N_NODES * EMB_DIM) return;
    int i = idx >> 7;
    int c = idx & 127;
    float v = sc[c] * g_agg2[idx] + sh[c];   // agg2 already relu(raw+b2)
    int g = batch[i];
    float* addr = out + g * EMB_DIM + c;
    if (v >= 0.f) atomicMax((int*)addr, __float_as_int(v));
    else          atomicMin((unsigned int*)addr, (unsigned int)__float_as_int(v));
}

// ---------------- launch ----------------
extern "C" void kernel_launch(void* const* d_in, const int* in_sizes, int n_in,
                              void* d_out, int out_size) {
    const float* x      = (const float*)d_in[0];
    const int*   ei     = (const int*)d_in[1];
    const int*   batch  = (const int*)d_in[2];
    const float* W1     = (const float*)d_in[3];
    const float* b1     = (const float*)d_in[4];
    const float* gamma1 = (const float*)d_in[5];
    const float* beta1  = (const float*)d_in[6];
    const float* W2     = (const float*)d_in[7];
    const float* b2     = (const float*)d_in[8];
    const float* gamma2 = (const float*)d_in[9];
    const float* beta2  = (const float*)d_in[10];
    float* out = (float*)d_out;

    const int* src = ei;
    const int* dst = ei + N_EDGES;

    float *p_agg1, *p_h1r, *p_h2, *p_agg2;
    cudaGetSymbolAddress((void**)&p_agg1, g_agg1);
    cudaGetSymbolAddress((void**)&p_h1r,  g_h1r);
    cudaGetSymbolAddress((void**)&p_h2,   g_h2);
    cudaGetSymbolAddress((void**)&p_agg2, g_agg2);

    const int SMEM1 = (IN_DIM * 136 + 2 * 32 * 136) * 4;              // 104448
    const int SMEM2 = (HID_DIM * 136 + 2 * 32 * 136 + 2 * HID_DIM) * 4; // 176128
    cudaFuncSetAttribute(k_mma<IN_DIM, HID_DIM, true, false, true>,
                         cudaFuncAttributeMaxDynamicSharedMemorySize, SMEM1);
    cudaFuncSetAttribute(k_mma<HID_DIM, EMB_DIM, false, true, false>,
                         cudaFuncAttributeMaxDynamicSharedMemorySize, SMEM2);
    const int MTILES = (N_NODES + 127) / 128;                         // 391

    // init + degrees + CSR build
    k_zero<<<(N_GRAPHS * EMB_DIM + 255) / 256, 256>>>(out);
    k_deg<<<(N_EDGES + 255) / 256, 256>>>(dst);
    k_scan1<<<SCAN_NBLK, SCAN_TPB>>>();
    k_scan2<<<1, 64>>>();
    k_scan3<<<(N_NODES + 255) / 256, 256>>>();
    k_fill<<<(N_EDGES + 255) / 256, 256>>>(src, dst);

    // layer 1: aggregate (linearity), then tf32 GEMM (+bias+relu+stats1)
    k_gather<false><<<(N_NODES * 32 + 255) / 256, 256>>>(x, p_agg1, nullptr);
    {
        dim3 grid(MTILES, HID_DIM / 128);
        k_mma<IN_DIM, HID_DIM, true, false, true><<<grid, 256, SMEM1>>>(
            p_agg1, W1, b1, nullptr, nullptr, p_h1r, N_NODES);
    }

    // layer 2: GEMM (bn1 computed in-kernel from stats), then aggregate (+b2+relu+stats2)
    {
        dim3 grid(MTILES, EMB_DIM / 128);
        k_mma<HID_DIM, EMB_DIM, false, true, false><<<grid, 256, SMEM2>>>(
            p_h1r, W2, nullptr, gamma1, beta1, p_h2, N_NODES);
    }
    k_gather<true><<<(N_NODES * 32 + 255) / 256, 256>>>(p_h2, p_agg2, b2);

    // output: segment-max with fused bn2
    k_segmax<<<(N_NODES * EMB_DIM + 255) / 256, 256>>>(gamma2, beta2, batch, out);
}

// round 7
// speedup vs baseline: 2.3525x; 1.0784x over previous
#include <cuda_runtime.h>
#include <cstdint>
#include <cstddef>

#define N_NODES  50000
#define N_EDGES  800000
#define N_GRAPHS 512
#define IN_DIM   128
#define HID_DIM  256
#define EMB_DIM  128
#define EPS_BN   1e-5f

#define SCAN_TPB 256
#define SCAN_EPB 1024
#define SCAN_NBLK ((N_NODES + SCAN_EPB - 1) / SCAN_EPB)   // 49

// ---------------- device scratch (static; no allocation allowed) ----------------
__device__ float g_agg1[(size_t)N_NODES * IN_DIM];   // A_norm(x)                 [N,128]
__device__ float g_h1r [(size_t)N_NODES * HID_DIM];  // relu(agg1@W1+b1)          [N,256]
__device__ float g_h2  [(size_t)N_NODES * EMB_DIM];  // bn1(h1r)@W2               [N,128]
__device__ int   g_deg [N_NODES];
__device__ int   g_rowoff[N_NODES];
__device__ int   g_cnt [N_NODES];
__device__ int   g_part[64];
__device__ int   g_csr_src[N_EDGES];
__device__ float g_coef  [N_EDGES];
__device__ float g_dinv[N_NODES];
__device__ float g_invdeg[N_NODES];
__device__ float g_sum1[HID_DIM], g_sq1[HID_DIM];
__device__ float g_sum2[EMB_DIM], g_sq2[EMB_DIM];
__device__ float g_vmax[N_GRAPHS * EMB_DIM];         // per-graph max of relu(agg2+b2)
__device__ float g_vmin[N_GRAPHS * EMB_DIM];         // per-graph min of relu(agg2+b2)

// ---------------- setup kernels ----------------
__global__ void k_zero() {
    int i = blockIdx.x * blockDim.x + threadIdx.x;
    if (i < N_NODES) { g_deg[i] = 0; g_cnt[i] = 0; }
    if (i < HID_DIM) { g_sum1[i] = 0.f; g_sq1[i] = 0.f; }
    if (i < EMB_DIM) { g_sum2[i] = 0.f; g_sq2[i] = 0.f; }
    if (i < N_GRAPHS * EMB_DIM) {
        g_vmax[i] = __int_as_float(0xFF800000);   // -inf
        g_vmin[i] = __int_as_float(0x7F800000);   // +inf
    }
}

__global__ void k_deg(const int* __restrict__ dst) {
    int e = blockIdx.x * blockDim.x + threadIdx.x;
    if (e < N_EDGES) atomicAdd(&g_deg[dst[e]], 1);
}

// exclusive scan of g_deg -> g_rowoff (3-phase); also computes dinv/invdeg
__global__ void k_scan1() {
    __shared__ int sh[SCAN_TPB / 32];
    int b = blockIdx.x, t = threadIdx.x;
    int base = b * SCAN_EPB + t * 4;
    int v[4]; int s = 0;
    #pragma unroll
    for (int q = 0; q < 4; q++) {
        int i = base + q;
        v[q] = (i < N_NODES) ? g_deg[i] : 0;
        s += v[q];
        if (i < N_NODES) {
            float d = (float)v[q] + 1.0f;
            g_dinv[i]   = rsqrtf(d);
            g_invdeg[i] = 1.0f / d;
        }
    }
    int x = s;
    #pragma unroll
    for (int off = 1; off < 32; off <<= 1) {
        int y = __shfl_up_sync(0xffffffffu, x, off);
        if ((t & 31) >= off) x += y;
    }
    if ((t & 31) == 31) sh[t >> 5] = x;
    __syncthreads();
    if (t < 32) {
        int y = (t < SCAN_TPB / 32) ? sh[t] : 0;
        #pragma unroll
        for (int off = 1; off < SCAN_TPB / 32; off <<= 1) {
            int z = __shfl_up_sync(0xffffffffu, y, off);
            if (t >= off) y += z;
        }
        if (t < SCAN_TPB / 32) sh[t] = y;
    }
    __syncthreads();
    int warpoff = (t >= 32) ? sh[(t >> 5) - 1] : 0;
    int run = warpoff + x - s;
    #pragma unroll
    for (int q = 0; q < 4; q++) { int i = base + q; if (i < N_NODES) g_rowoff[i] = run; run += v[q]; }
    if (t == SCAN_TPB - 1) g_part[b] = warpoff + x;
}

__global__ void k_scan2() {
    __shared__ int sh[64];
    int t = threadIdx.x;
    int v = (t < SCAN_NBLK) ? g_part[t] : 0;
    sh[t] = v; __syncthreads();
    for (int off = 1; off < 64; off <<= 1) {
        int y = (t >= off) ? sh[t - off] : 0;
        __syncthreads();
        sh[t] += y;
        __syncthreads();
    }
    g_part[t] = sh[t] - v;
}

__global__ void k_scan3() {
    int i = blockIdx.x * blockDim.x + threadIdx.x;
    if (i < N_NODES) g_rowoff[i] += g_part[i / SCAN_EPB];
}

__global__ void k_fill(const int* __restrict__ src, const int* __restrict__ dst) {
    int e = blockIdx.x * blockDim.x + threadIdx.x;
    if (e >= N_EDGES) return;
    int d = dst[e], s = src[e];
    int pos = g_rowoff[d] + atomicAdd(&g_cnt[d], 1);
    g_csr_src[pos] = s;
    g_coef[pos] = g_dinv[s] * g_dinv[d];
}

// ---------------- gather aggregation: warp per node (D = 128) ----------------
// FUSE2: v = relu(acc + b2); accumulate stats2; per-graph max/min (batch sorted)
//        WITHOUT materializing agg2. No global store of features at all.
template <bool FUSE2>
__global__ void k_gather(const float* __restrict__ feat, float* __restrict__ agg,
                         const float* __restrict__ bias, const int* __restrict__ batch) {
    __shared__ float ssum[FUSE2 ? 128 : 1];
    __shared__ float ssq [FUSE2 ? 128 : 1];
    __shared__ float sv  [FUSE2 ? 8 * 128 : 1];
    __shared__ int   sb  [FUSE2 ? 8 : 1];
    int tid = threadIdx.x;
    if (FUSE2) {
        if (tid < 128) { ssum[tid] = 0.f; ssq[tid] = 0.f; }
    }
    int w = (blockIdx.x * blockDim.x + tid) >> 5;
    int lane = tid & 31;
    int wrp = tid >> 5;
    const float4* feat4 = (const float4*)feat;

    float4 acc = feat4[(size_t)w * 32 + lane];
    float selfw = g_invdeg[w];
    acc.x *= selfw; acc.y *= selfw; acc.z *= selfw; acc.w *= selfw;

    int start = g_rowoff[w];
    int end   = start + g_deg[w];
    for (int base = start; base < end; base += 32) {
        int e = base + lane;
        int   s_l = 0;
        float c_l = 0.f;
        if (e < end) { s_l = g_csr_src[e]; c_l = g_coef[e]; }
        int cnt = min(32, end - base);
        for (int j = 0; j < cnt; j++) {
            int   s = __shfl_sync(0xffffffffu, s_l, j);
            float c = __shfl_sync(0xffffffffu, c_l, j);
            float4 v = feat4[(size_t)s * 32 + lane];
            acc.x = fmaf(v.x, c, acc.x);
            acc.y = fmaf(v.y, c, acc.y);
            acc.z = fmaf(v.z, c, acc.z);
            acc.w = fmaf(v.w, c, acc.w);
        }
    }
    if (!FUSE2) {
        ((float4*)agg)[(size_t)w * 32 + lane] = acc;
    } else {
        float4 b = ((const float4*)bias)[lane];
        acc.x = fmaxf(acc.x + b.x, 0.f);
        acc.y = fmaxf(acc.y + b.y, 0.f);
        acc.z = fmaxf(acc.z + b.z, 0.f);
        acc.w = fmaxf(acc.w + b.w, 0.f);
        // stats
        atomicAdd(&ssum[lane * 4 + 0], acc.x);
        atomicAdd(&ssum[lane * 4 + 1], acc.y);
        atomicAdd(&ssum[lane * 4 + 2], acc.z);
        atomicAdd(&ssum[lane * 4 + 3], acc.w);
        atomicAdd(&ssq[lane * 4 + 0], acc.x * acc.x);
        atomicAdd(&ssq[lane * 4 + 1], acc.y * acc.y);
        atomicAdd(&ssq[lane * 4 + 2], acc.z * acc.z);
        atomicAdd(&ssq[lane * 4 + 3], acc.w * acc.w);
        // stage values for per-block segmented max/min
        *(float4*)&sv[wrp * 128 + lane * 4] = acc;
        if (lane == 0) sb[wrp] = batch[w];
        __syncthreads();
        if (tid < 128) {
            atomicAdd(&g_sum2[tid], ssum[tid]);
            atomicAdd(&g_sq2[tid], ssq[tid]);
            float rmax = __int_as_float(0xFF800000);
            float rmin = __int_as_float(0x7F800000);
            int cur = sb[0];
            #pragma unroll
            for (int ww = 0; ww < 8; ww++) {
                int bid = sb[ww];
                if (bid != cur) {
                    // v >= 0 so int compare is order-preserving
                    atomicMax((int*)&g_vmax[cur * 128 + tid], __float_as_int(rmax));
                    atomicMin((int*)&g_vmin[cur * 128 + tid], __float_as_int(rmin));
                    rmax = __int_as_float(0xFF800000);
                    rmin = __int_as_float(0x7F800000);
                    cur = bid;
                }
                float vv = sv[ww * 128 + tid];
                rmax = fmaxf(rmax, vv);
                rmin = fminf(rmin, vv);
            }
            atomicMax((int*)&g_vmax[cur * 128 + tid], __float_as_int(rmax));
            atomicMin((int*)&g_vmin[cur * 128 + tid], __float_as_int(rmin));
        }
    }
}

// ================= tf32 mma.sync GEMM =================
__device__ __forceinline__ uint32_t f2tf32(float f) {
    uint32_t r; asm("cvt.rna.tf32.f32 %0, %1;" : "=r"(r) : "f"(f)); return r;
}
__device__ __forceinline__ void mma8(float& c0, float& c1, float& c2, float& c3,
                                     uint32_t a0, uint32_t a1, uint32_t a2, uint32_t a3,
                                     uint32_t b0, uint32_t b1) {
    asm volatile(
        "mma.sync.aligned.m16n8k8.row.col.f32.tf32.tf32.f32 "
        "{%0,%1,%2,%3}, {%4,%5,%6,%7}, {%8,%9}, {%0,%1,%2,%3};"
        : "+f"(c0), "+f"(c1), "+f"(c2), "+f"(c3)
        : "r"(a0), "r"(a1), "r"(a2), "r"(a3), "r"(b0), "r"(b1));
}

// C[M,NC] = (NORM? bn1(A) : A)[M,KD] @ W[KD,NC] (+bias,relu)
// CTA tile 128x128; 8 warps 4(M)x2(N); warp tile 32x64; tf32 HMMA.
template <int KD, int NC, bool RELU, bool NORM, bool STATS>
__global__ __launch_bounds__(256) void k_mma(const float* __restrict__ A,
                                             const float* __restrict__ W,
                                             const float* __restrict__ bias,
                                             const float* __restrict__ gamma,
                                             const float* __restrict__ beta,
                                             float* __restrict__ C, int M) {
    constexpr int STR = 136;
    constexpr int NCHUNK = KD / 32;
    extern __shared__ uint32_t smem_u[];
    uint32_t* Bs = smem_u;               // KD * STR
    uint32_t* As = smem_u + KD * STR;    // 2 * 32 * STR
    float* sc1 = (float*)(smem_u + KD * STR + 2 * 32 * STR);       // [KD] when NORM
    float* sh1 = sc1 + (NORM ? KD : 0);

    const int tid  = threadIdx.x;
    const int wid  = tid >> 5;
    const int lane = tid & 31;
    const int g = lane >> 2, t = lane & 3;
    const int wm = wid & 3, wn = wid >> 2;
    const int bm = blockIdx.x * 128;
    const int bn = blockIdx.y * 128;

    if (NORM) {
        const float invM = 1.0f / (float)N_NODES;
        for (int i = tid; i < KD; i += 256) {
            float m = g_sum1[i] * invM;
            float var = g_sq1[i] * invM - m * m;
            float sc = gamma[i] * rsqrtf(var + EPS_BN);
            sc1[i] = sc;
            sh1[i] = beta[i] - m * sc;
        }
    }

    // ---- load B tile (cols [bn,bn+128)) as tf32 ----
    for (int i = tid; i < KD * 32; i += 256) {
        int k = i >> 5;
        int n = (i & 31) * 4;
        float4 w = *(const float4*)(W + (size_t)k * NC + bn + n);
        uint4 u;
        u.x = f2tf32(w.x); u.y = f2tf32(w.y); u.z = f2tf32(w.z); u.w = f2tf32(w.w);
        *(uint4*)&Bs[k * STR + n] = u;
    }
    if (NORM) __syncthreads();   // sc1/sh1 ready before loadA uses them

    const int la_row = tid >> 1;
    const int la_k   = (tid & 1) * 16;
    const int gr_a   = bm + la_row;

    float acc[2][8][4];
    #pragma unroll
    for (int f = 0; f < 2; f++)
        #pragma unroll
        for (int j = 0; j < 8; j++)
            #pragma unroll
            for (int q = 0; q < 4; q++) acc[f][j][q] = 0.f;

    auto loadA = [&](int c, float4* pre) {
        int k0 = c * 32 + la_k;
        #pragma unroll
        for (int i = 0; i < 4; i++) {
            float4 v = make_float4(0.f, 0.f, 0.f, 0.f);
            if (gr_a < M) v = *(const float4*)(A + (size_t)gr_a * KD + k0 + i * 4);
            if (NORM) {
                int kk = k0 + i * 4;
                v.x = fmaf(v.x, sc1[kk + 0], sh1[kk + 0]);
                v.y = fmaf(v.y, sc1[kk + 1], sh1[kk + 1]);
                v.z = fmaf(v.z, sc1[kk + 2], sh1[kk + 2]);
                v.w = fmaf(v.w, sc1[kk + 3], sh1[kk + 3]);
            }
            pre[i] = v;
        }
    };
    auto storeA = [&](int buf, const float4* pre) {
        uint32_t* Ab = As + buf * (32 * STR);
        #pragma unroll
        for (int i = 0; i < 4; i++) {
            int kl = la_k + i * 4;
            Ab[(kl + 0) * STR + la_row] = f2tf32(pre[i].x);
            Ab[(kl + 1) * STR + la_row] = f2tf32(pre[i].y);
            Ab[(kl + 2) * STR + la_row] = f2tf32(pre[i].z);
            Ab[(kl + 3) * STR + la_row] = f2tf32(pre[i].w);
        }
    };
    auto compute = [&](int buf, int c) {
        const uint32_t* Ab = As + buf * (32 * STR);
        #pragma unroll
        for (int ks = 0; ks < 4; ks++) {
            int kt = ks * 8 + t;
            uint32_t a[2][4];
            #pragma unroll
            for (int f = 0; f < 2; f++) {
                int row = wm * 32 + f * 16 + g;
                a[f][0] = Ab[kt * STR + row];
                a[f][1] = Ab[kt * STR + row + 8];
                a[f][2] = Ab[(kt + 4) * STR + row];
                a[f][3] = Ab[(kt + 4) * STR + row + 8];
            }
            int kabs = c * 32 + ks * 8 + t;
            #pragma unroll
            for (int j = 0; j < 8; j++) {
                int col = wn * 64 + j * 8 + g;
                uint32_t b0 = Bs[kabs * STR + col];
                uint32_t b1 = Bs[(kabs + 4) * STR + col];
                mma8(acc[0][j][0], acc[0][j][1], acc[0][j][2], acc[0][j][3],
                     a[0][0], a[0][1], a[0][2], a[0][3], b0, b1);
                mma8(acc[1][j][0], acc[1][j][1], acc[1][j][2], acc[1][j][3],
                     a[1][0], a[1][1], a[1][2], a[1][3], b0, b1);
            }
        }
    };

    float4 pre[4];
    loadA(0, pre);
    storeA(0, pre);
    __syncthreads();
    int buf = 0;
    for (int c = 1; c < NCHUNK; c++) {
        loadA(c, pre);
        compute(buf, c - 1);
        storeA(buf ^ 1, pre);
        __syncthreads();
        buf ^= 1;
    }
    compute(buf, NCHUNK - 1);

    // ---- epilogue: regs -> gmem (+bias,relu) ; fused stats ----
    #pragma unroll
    for (int f = 0; f < 2; f++) {
        int r0 = bm + wm * 32 + f * 16 + g;
        #pragma unroll
        for (int j = 0; j < 8; j++) {
            int gc = bn + wn * 64 + j * 8 + 2 * t;
            float2 v0 = make_float2(acc[f][j][0], acc[f][j][1]);
            float2 v1 = make_float2(acc[f][j][2], acc[f][j][3]);
            if (RELU) {
                float b0v = bias[gc], b1v = bias[gc + 1];
                v0.x = fmaxf(v0.x + b0v, 0.f); v0.y = fmaxf(v0.y + b1v, 0.f);
                v1.x = fmaxf(v1.x + b0v, 0.f); v1.y = fmaxf(v1.y + b1v, 0.f);
            }
            if (r0 < M)     *(float2*)(C + (size_t)r0 * NC + gc)       = v0;
            if (r0 + 8 < M) *(float2*)(C + (size_t)(r0 + 8) * NC + gc) = v1;
            if (STATS) {
                bool m0 = r0 < M, m1 = (r0 + 8) < M;
                float s0 = (m0 ? v0.x : 0.f) + (m1 ? v1.x : 0.f);
                float s1 = (m0 ? v0.y : 0.f) + (m1 ? v1.y : 0.f);
                float q0 = (m0 ? v0.x * v0.x : 0.f) + (m1 ? v1.x * v1.x : 0.f);
                float q1 = (m0 ? v0.y * v0.y : 0.f) + (m1 ? v1.y * v1.y : 0.f);
                #pragma unroll
                for (int off = 4; off < 32; off <<= 1) {
                    s0 += __shfl_xor_sync(0xffffffffu, s0, off);
                    s1 += __shfl_xor_sync(0xffffffffu, s1, off);
                    q0 += __shfl_xor_sync(0xffffffffu, q0, off);
                    q1 += __shfl_xor_sync(0xffffffffu, q1, off);
                }
                if (lane < 4) {
                    int cc = bn + wn * 64 + j * 8 + 2 * lane;
                    atomicAdd(&g_sum1[cc], s0);
                    atomicAdd(&g_sum1[cc + 1], s1);
                    atomicAdd(&g_sq1[cc], q0);
                    atomicAdd(&g_sq1[cc + 1], q1);
                }
            }
        }
    }
}

// ---------------- final: apply BN2 affine to per-graph max/min ----------------
__global__ void k_final(const float* __restrict__ gamma, const float* __restrict__ beta,
                        float* __restrict__ out) {
    __shared__ float sc[EMB_DIM], sh[EMB_DIM];
    int tid = threadIdx.x;
    if (tid < EMB_DIM) {
        const float invM = 1.0f / (float)N_NODES;
        float m = g_sum2[tid] * invM;
        float var = g_sq2[tid] * invM - m * m;
        float s = gamma[tid] * rsqrtf(var + EPS_BN);
        sc[tid] = s;
        sh[tid] = beta[tid] - m * s;
    }
    __syncthreads();
    int idx = blockIdx.x * blockDim.x + tid;
    if (idx >= N_GRAPHS * EMB_DIM) return;
    int c = idx & 127;
    float s = sc[c];
    float v = (s >= 0.f) ? g_vmax[idx] : g_vmin[idx];
    out[idx] = fmaf(s, v, sh[c]);
}

// ---------------- launch ----------------
extern "C" void kernel_launch(void* const* d_in, const int* in_sizes, int n_in,
                              void* d_out, int out_size) {
    const float* x      = (const float*)d_in[0];
    const int*   ei     = (const int*)d_in[1];
    const int*   batch  = (const int*)d_in[2];
    const float* W1     = (const float*)d_in[3];
    const float* b1     = (const float*)d_in[4];
    const float* gamma1 = (const float*)d_in[5];
    const float* beta1  = (const float*)d_in[6];
    const float* W2     = (const float*)d_in[7];
    const float* b2     = (const float*)d_in[8];
    const float* gamma2 = (const float*)d_in[9];
    const float* beta2  = (const float*)d_in[10];
    float* out = (float*)d_out;

    const int* src = ei;
    const int* dst = ei + N_EDGES;

    float *p_agg1, *p_h1r, *p_h2;
    cudaGetSymbolAddress((void**)&p_agg1, g_agg1);
    cudaGetSymbolAddress((void**)&p_h1r,  g_h1r);
    cudaGetSymbolAddress((void**)&p_h2,   g_h2);

    const int SMEM1 = (IN_DIM * 136 + 2 * 32 * 136) * 4;                // 104448
    const int SMEM2 = (HID_DIM * 136 + 2 * 32 * 136 + 2 * HID_DIM) * 4; // 176128
    cudaFuncSetAttribute(k_mma<IN_DIM, HID_DIM, true, false, true>,
                         cudaFuncAttributeMaxDynamicSharedMemorySize, SMEM1);
    cudaFuncSetAttribute(k_mma<HID_DIM, EMB_DIM, false, true, false>,
                         cudaFuncAttributeMaxDynamicSharedMemorySize, SMEM2);
    const int MTILES = (N_NODES + 127) / 128;                           // 391

    // init + degrees + CSR build
    k_zero<<<(N_GRAPHS * EMB_DIM + 255) / 256, 256>>>();
    k_deg<<<(N_EDGES + 255) / 256, 256>>>(dst);
    k_scan1<<<SCAN_NBLK, SCAN_TPB>>>();
    k_scan2<<<1, 64>>>();
    k_scan3<<<(N_NODES + 255) / 256, 256>>>();
    k_fill<<<(N_EDGES + 255) / 256, 256>>>(src, dst);

    // layer 1: aggregate (linearity), then tf32 GEMM (+bias+relu+stats1)
    k_gather<false><<<(N_NODES * 32 + 255) / 256, 256>>>(x, p_agg1, nullptr, nullptr);
    {
        dim3 grid(MTILES, HID_DIM / 128);
        k_mma<IN_DIM, HID_DIM, true, false, true><<<grid, 256, SMEM1>>>(
            p_agg1, W1, b1, nullptr, nullptr, p_h1r, N_NODES);
    }

    // layer 2: GEMM (bn1 in-kernel from stats), then fused aggregate+stats2+segmax
    {
        dim3 grid(MTILES, EMB_DIM / 128);
        k_mma<HID_DIM, EMB_DIM, false, true, false><<<grid, 256, SMEM2>>>(
            p_h1r, W2, nullptr, gamma1, beta1, p_h2, N_NODES);
    }
    k_gather<true><<<(N_NODES * 32 + 255) / 256, 256>>>(p_h2, nullptr, b2, batch);

    // output: BN2 affine on per-graph extrema
    k_final<<<(N_GRAPHS * EMB_DIM + 255) / 256, 256>>>(gamma2, beta2, out);
}